// round 3
// baseline (speedup 1.0000x reference)
#include <cuda_runtime.h>
#include <math.h>

// Problem constants
#define NN   100000
#define EE   1600000
#define HID  128
#define DIN  6
#define OUTD 2
#define SLOPE 0.2f

#define SCAN_B 1024
#define NB ((NN + SCAN_B - 1) / SCAN_B)   // 98

// ---------------- device scratch ----------------
__device__ float g_h    [NN * HID];
__device__ float g_h1   [NN * HID];
__device__ float g_hx   [NN * HID];
__device__ float g_asrc [NN];
__device__ float g_adst [NN];
__device__ float g_alpha[EE];
__device__ int   g_src  [EE];         // int32 source indices
__device__ int   g_dst  [EE];         // int32 dest indices
__device__ int   g_counts [NN];
__device__ int   g_offsets[NN + 1];
__device__ int   g_cursor [NN];
__device__ int   g_csr    [EE];
__device__ int   g_bsum   [NB];
__device__ float g_cedge;
__device__ int   g_is64;              // 1 if edge_index buffer is int64

// ---------------- dtype probe + convert ----------------

// If the buffer holds int64 values < 2^31, every odd int32 word is zero.
__global__ void k_detect(const int* __restrict__ ei32) {
    __shared__ int nz;
    if (threadIdx.x == 0) nz = 0;
    __syncthreads();
    int found = 0;
    for (int i = threadIdx.x; i < 4096; i += blockDim.x) {
        if (ei32[2 * i + 1] != 0) found = 1;
    }
    if (found) atomicAdd(&nz, 1);
    __syncthreads();
    if (threadIdx.x == 0) g_is64 = (nz == 0) ? 1 : 0;
}

__global__ void k_convert(const void* __restrict__ ei) {
    int e = blockIdx.x * blockDim.x + threadIdx.x;
    if (e >= EE) return;
    if (g_is64) {
        const long long* p = (const long long*)ei;
        g_src[e] = (int)p[e];
        g_dst[e] = (int)p[EE + e];
    } else {
        const int* p = (const int*)ei;
        g_src[e] = p[e];
        g_dst[e] = p[EE + e];
    }
}

// ---------------- kernels ----------------

__global__ void k_init_counts() {
    int i = blockIdx.x * blockDim.x + threadIdx.x;
    if (i < NN) g_counts[i] = 0;
}

__global__ void k_calc_cedge(const float* __restrict__ w_edge,
                             const float* __restrict__ att_edge) {
    __shared__ float sred[128];
    int tid = threadIdx.x;
    sred[tid] = w_edge[tid] * att_edge[tid];
    __syncthreads();
    for (int s = 64; s > 0; s >>= 1) {
        if (tid < s) sred[tid] += sred[tid + s];
        __syncthreads();
    }
    if (tid == 0) g_cedge = sred[0];
}

// one block per node: h = x @ w_gat ; a_src = h . att_src ; a_dst = h . att_dst
__global__ __launch_bounds__(128) void k_node_transform(
    const float* __restrict__ x, const float* __restrict__ w_gat,
    const float* __restrict__ att_src, const float* __restrict__ att_dst) {
    int n = blockIdx.x;
    int j = threadIdx.x;
    float xr[DIN];
#pragma unroll
    for (int k = 0; k < DIN; k++) xr[k] = x[n * DIN + k];
    float hj = 0.f;
#pragma unroll
    for (int k = 0; k < DIN; k++) hj += xr[k] * w_gat[k * HID + j];
    g_h[(long)n * HID + j] = hj;

    __shared__ float sred[256];
    sred[j]       = hj * att_src[j];
    sred[128 + j] = hj * att_dst[j];
    __syncthreads();
    for (int s = 64; s > 0; s >>= 1) {
        if (j < s) { sred[j] += sred[j + s]; sred[128 + j] += sred[128 + j + s]; }
        __syncthreads();
    }
    if (j == 0) { g_asrc[n] = sred[0]; g_adst[n] = sred[128]; }
}

__global__ void k_count() {
    int e = blockIdx.x * blockDim.x + threadIdx.x;
    if (e < EE) atomicAdd(&g_counts[g_dst[e]], 1);
}

// exclusive scan over g_counts -> g_offsets
__global__ void k_scan1() {
    __shared__ int s[SCAN_B];
    int tid = threadIdx.x;
    int gi = blockIdx.x * SCAN_B + tid;
    int v = (gi < NN) ? g_counts[gi] : 0;
    s[tid] = v;
    __syncthreads();
    for (int off = 1; off < SCAN_B; off <<= 1) {
        int t = (tid >= off) ? s[tid - off] : 0;
        __syncthreads();
        s[tid] += t;
        __syncthreads();
    }
    if (gi < NN) g_offsets[gi] = s[tid] - v;
    if (tid == SCAN_B - 1) g_bsum[blockIdx.x] = s[tid];
}

__global__ void k_scan2() {
    int acc = 0;
    for (int b = 0; b < NB; b++) {
        int v = g_bsum[b];
        g_bsum[b] = acc;
        acc += v;
    }
}

__global__ void k_scan3() {
    int tid = threadIdx.x;
    int gi = blockIdx.x * SCAN_B + tid;
    if (gi < NN) {
        int o = g_offsets[gi] + g_bsum[blockIdx.x];
        g_offsets[gi] = o;
        g_cursor[gi]  = o;
    }
    if (gi == 0) g_offsets[NN] = EE;
}

__global__ void k_scatter() {
    int e = blockIdx.x * blockDim.x + threadIdx.x;
    if (e < EE) {
        int pos = atomicAdd(&g_cursor[g_dst[e]], 1);
        g_csr[pos] = e;
    }
}

// one block (128 thr) per dst node: segment softmax + GAT aggregation
__global__ __launch_bounds__(128) void k_gat(
    const float* __restrict__ ew, const float* __restrict__ b_gat) {
    int n = blockIdx.x;
    int tid = threadIdx.x;
    int off = g_offsets[n];
    int deg = g_offsets[n + 1] - off;
    float adst_n = g_adst[n];
    float c = g_cedge;

    __shared__ float sred[128];
    __shared__ int   s_src[128];
    __shared__ float s_a[128];

    // pass 1: max logit
    float lmax = -3.0e38f;
    for (int i = tid; i < deg; i += 128) {
        int e = g_csr[off + i];
        float l = g_asrc[g_src[e]] + adst_n + c * ew[e];
        l = (l > 0.f) ? l : SLOPE * l;
        lmax = fmaxf(lmax, l);
    }
    sred[tid] = lmax;
    __syncthreads();
    for (int s = 64; s > 0; s >>= 1) {
        if (tid < s) sred[tid] = fmaxf(sred[tid], sred[tid + s]);
        __syncthreads();
    }
    float m = sred[0];
    __syncthreads();

    // pass 2: exp(l - m), accumulate denom
    float lsum = 0.f;
    for (int i = tid; i < deg; i += 128) {
        int e = g_csr[off + i];
        float l = g_asrc[g_src[e]] + adst_n + c * ew[e];
        l = (l > 0.f) ? l : SLOPE * l;
        float ev = __expf(l - m);
        g_alpha[e] = ev;
        lsum += ev;
    }
    sred[tid] = lsum;
    __syncthreads();
    for (int s = 64; s > 0; s >>= 1) {
        if (tid < s) sred[tid] += sred[tid + s];
        __syncthreads();
    }
    float denom = fmaxf(sred[0], 1e-16f);
    float invd = 1.f / denom;
    __syncthreads();

    // pass 3: normalize alpha + aggregate
    float acc = 0.f;
    for (int chunk = 0; chunk < deg; chunk += 128) {
        int i = chunk + tid;
        if (i < deg) {
            int e = g_csr[off + i];
            s_src[tid] = g_src[e];
            float a = g_alpha[e] * invd;
            g_alpha[e] = a;
            s_a[tid] = a;
        }
        __syncthreads();
        int cend = min(128, deg - chunk);
#pragma unroll 4
        for (int k = 0; k < cend; k++)
            acc += s_a[k] * g_h[(long)s_src[k] * HID + tid];
        __syncthreads();
    }
    float hg = acc + b_gat[tid];
    g_h1[(long)n * HID + tid] = (hg > 0.f) ? hg : 0.f;
}

// hx = h1 @ w_gcn : 8 nodes per block
__global__ __launch_bounds__(256) void k_gemm(const float* __restrict__ w_gcn) {
    int n0 = blockIdx.x * 8;
    __shared__ float sh[8][HID];
    for (int i = threadIdx.x; i < 8 * HID; i += 256) {
        int r = i >> 7, cidx = i & 127;
        sh[r][cidx] = g_h1[(long)(n0 + r) * HID + cidx];
    }
    __syncthreads();
    int local = threadIdx.x >> 5;
    int jc = (threadIdx.x & 31) * 4;
    float4 acc = make_float4(0.f, 0.f, 0.f, 0.f);
#pragma unroll 8
    for (int k = 0; k < HID; k++) {
        float a = sh[local][k];
        float4 w = *(const float4*)&w_gcn[k * HID + jc];
        acc.x += a * w.x; acc.y += a * w.y; acc.z += a * w.z; acc.w += a * w.w;
    }
    *(float4*)&g_hx[(long)(n0 + local) * HID + jc] = acc;
}

// one block per dst node: GCN aggregation + relu + output head
__global__ __launch_bounds__(128) void k_gcn_out(
    const float* __restrict__ b_gcn, const float* __restrict__ w_out,
    const float* __restrict__ b_out, float* __restrict__ out) {
    int n = blockIdx.x;
    int tid = threadIdx.x;
    int off = g_offsets[n];
    int deg = g_offsets[n + 1] - off;

    __shared__ int   s_src[128];
    __shared__ float s_w[128];
    __shared__ float sred[256];

    float acc = 0.f;
    for (int chunk = 0; chunk < deg; chunk += 128) {
        int i = chunk + tid;
        if (i < deg) {
            int e = g_csr[off + i];
            int s = g_src[e];
            s_src[tid] = s;
            // norm = dinv[src]*alpha*dinv[dst]; deg==sum(alpha)==1 for any node
            // with incoming edges, so dinv is an indicator.
            s_w[tid] = g_alpha[e] * ((g_counts[s] > 0) ? 1.f : 0.f);
        }
        __syncthreads();
        int cend = min(128, deg - chunk);
#pragma unroll 4
        for (int k = 0; k < cend; k++)
            acc += s_w[k] * g_hx[(long)s_src[k] * HID + tid];
        __syncthreads();
    }
    float h2 = acc + b_gcn[tid];
    h2 = (h2 > 0.f) ? h2 : 0.f;

    sred[tid]       = h2 * w_out[tid * 2 + 0];
    sred[128 + tid] = h2 * w_out[tid * 2 + 1];
    __syncthreads();
    for (int s = 64; s > 0; s >>= 1) {
        if (tid < s) { sred[tid] += sred[tid + s]; sred[128 + tid] += sred[128 + tid + s]; }
        __syncthreads();
    }
    if (tid == 0) {
        out[n * 2 + 0] = sred[0]   + b_out[0];
        out[n * 2 + 1] = sred[128] + b_out[1];
    }
}

__global__ void k_copy_ei_f(float* __restrict__ dst) {
    int i = blockIdx.x * blockDim.x + threadIdx.x;
    if (i < EE) dst[i] = (float)g_src[i];
    else if (i < 2 * EE) dst[i] = (float)g_dst[i - EE];
}

__global__ void k_copy_alpha(float* __restrict__ dst) {
    int i = blockIdx.x * blockDim.x + threadIdx.x;
    if (i < EE) dst[i] = g_alpha[i];
}

// ---------------- launch ----------------
extern "C" void kernel_launch(void* const* d_in, const int* in_sizes, int n_in,
                              void* d_out, int out_size) {
    int iei, iew, iwg, ias, iad, iwe, iae, ibg, iwgcn, ibgcn, iwo, ibo;
    if (in_sizes[1] == 2 * EE) {
        iei = 1; iew = 2; iwg = 3; ias = 4; iad = 5; iwe = 6; iae = 7;
        ibg = 8; iwgcn = 9; ibgcn = 10; iwo = 11; ibo = 12;
    } else {
        iew = 1; iwg = 2; ias = 3; iad = 4; iwe = 5; iae = 6; ibg = 7;
        iwgcn = 8; ibgcn = 9; iwo = 10; ibo = 11; iei = 12;
    }

    const float* x        = (const float*)d_in[0];
    const void*  ei       = d_in[iei];
    const float* ew       = (const float*)d_in[iew];
    const float* w_gat    = (const float*)d_in[iwg];
    const float* att_src  = (const float*)d_in[ias];
    const float* att_dst  = (const float*)d_in[iad];
    const float* w_edge   = (const float*)d_in[iwe];
    const float* att_edge = (const float*)d_in[iae];
    const float* b_gat    = (const float*)d_in[ibg];
    const float* w_gcn    = (const float*)d_in[iwgcn];
    const float* b_gcn    = (const float*)d_in[ibgcn];
    const float* w_out    = (const float*)d_in[iwo];
    const float* b_out    = (const float*)d_in[ibo];
    float*       out      = (float*)d_out;

    k_detect<<<1, 256>>>((const int*)ei);
    k_convert<<<(EE + 255) / 256, 256>>>(ei);
    k_init_counts<<<(NN + 255) / 256, 256>>>();
    k_calc_cedge<<<1, 128>>>(w_edge, att_edge);
    k_node_transform<<<NN, 128>>>(x, w_gat, att_src, att_dst);
    k_count<<<(EE + 255) / 256, 256>>>();
    k_scan1<<<NB, SCAN_B>>>();
    k_scan2<<<1, 1>>>();
    k_scan3<<<NB, SCAN_B>>>();
    k_scatter<<<(EE + 255) / 256, 256>>>();
    k_gat<<<NN, 128>>>(ew, b_gat);
    k_gemm<<<NN / 8, 256>>>(w_gcn);
    k_gcn_out<<<NN, 128>>>(b_gcn, w_out, b_out, out);

    int rem = out_size - NN * OUTD;
    if (rem == EE) {
        k_copy_alpha<<<(EE + 255) / 256, 256>>>(out + NN * OUTD);
    } else if (rem == 3 * EE) {
        k_copy_ei_f<<<(2 * EE + 255) / 256, 256>>>(out + NN * OUTD);
        k_copy_alpha<<<(EE + 255) / 256, 256>>>(out + NN * OUTD + 2 * EE);
    }
}

// round 4
// speedup vs baseline: 1.4540x; 1.4540x over previous
#include <cuda_runtime.h>
#include <math.h>

#define NN   100000
#define EE   1600000
#define HID  128
#define DIN  6
#define OUTD 2
#define SLOPE 0.2f

#define SCAN_B 1024
#define NB ((NN + SCAN_B - 1) / SCAN_B)   // 98

// ---------------- device scratch ----------------
__device__ float g_h    [NN * HID];
__device__ float g_h1   [NN * HID];
__device__ float g_hx   [NN * HID];
__device__ float g_asrc [NN];
__device__ float g_adst [NN];
__device__ float g_ind  [NN];         // 1.0 if node has incoming edges
__device__ float g_alphap[EE];        // logits -> exp -> alpha, CSR (dst-grouped) order
__device__ int   g_src  [EE];
__device__ int   g_dst  [EE];
__device__ int   g_srcp [EE];         // src index in CSR order
__device__ float g_ewp  [EE];         // edge weight in CSR order
__device__ int   g_eid  [EE];         // original edge id per CSR pos (for alpha writeback)
__device__ int   g_counts [NN];
__device__ int   g_offsets[NN + 1];
__device__ int   g_cursor [NN];
__device__ int   g_bsum   [NB];
__device__ float g_cedge;
__device__ int   g_is64;

// ---------------- f32x2 helpers (Blackwell packed FFMA2) ----------------
__device__ __forceinline__ unsigned long long pack2(float a, float b) {
    unsigned long long r;
    asm("mov.b64 %0, {%1, %2};" : "=l"(r) : "f"(a), "f"(b));
    return r;
}
__device__ __forceinline__ void unpack2(unsigned long long v, float& a, float& b) {
    asm("mov.b64 {%0, %1}, %2;" : "=f"(a), "=f"(b) : "l"(v));
}
__device__ __forceinline__ unsigned long long fma2(
    unsigned long long a, unsigned long long b, unsigned long long c) {
    unsigned long long d;
    asm("fma.rn.f32x2 %0, %1, %2, %3;" : "=l"(d) : "l"(a), "l"(b), "l"(c));
    return d;
}

// ---------------- block reductions (128 threads) ----------------
__device__ __forceinline__ float bred_max128(float v) {
#pragma unroll
    for (int o = 16; o > 0; o >>= 1) v = fmaxf(v, __shfl_xor_sync(0xffffffffu, v, o));
    __shared__ float s4[4];
    __syncthreads();
    if ((threadIdx.x & 31) == 0) s4[threadIdx.x >> 5] = v;
    __syncthreads();
    return fmaxf(fmaxf(s4[0], s4[1]), fmaxf(s4[2], s4[3]));
}
__device__ __forceinline__ float bred_sum128(float v) {
#pragma unroll
    for (int o = 16; o > 0; o >>= 1) v += __shfl_xor_sync(0xffffffffu, v, o);
    __shared__ float s4b[4];
    __syncthreads();
    if ((threadIdx.x & 31) == 0) s4b[threadIdx.x >> 5] = v;
    __syncthreads();
    return s4b[0] + s4b[1] + s4b[2] + s4b[3];
}

// ---------------- dtype probe + convert ----------------
__global__ void k_detect(const int* __restrict__ ei32) {
    __shared__ int nz;
    if (threadIdx.x == 0) nz = 0;
    __syncthreads();
    int found = 0;
    for (int i = threadIdx.x; i < 4096; i += blockDim.x)
        if (ei32[2 * i + 1] != 0) found = 1;
    if (found) atomicAdd(&nz, 1);
    __syncthreads();
    if (threadIdx.x == 0) g_is64 = (nz == 0) ? 1 : 0;
}

__global__ void k_convert(const void* __restrict__ ei) {
    int e = blockIdx.x * blockDim.x + threadIdx.x;
    if (e >= EE) return;
    if (g_is64) {
        const long long* p = (const long long*)ei;
        g_src[e] = (int)p[e];
        g_dst[e] = (int)p[EE + e];
    } else {
        const int* p = (const int*)ei;
        g_src[e] = p[e];
        g_dst[e] = p[EE + e];
    }
}

// ---------------- small kernels ----------------
__global__ void k_init_counts() {
    int i = blockIdx.x * blockDim.x + threadIdx.x;
    if (i < NN) g_counts[i] = 0;
}

__global__ void k_calc_cedge(const float* __restrict__ w_edge,
                             const float* __restrict__ att_edge) {
    int tid = threadIdx.x;
    float v = w_edge[tid] * att_edge[tid];
#pragma unroll
    for (int o = 16; o > 0; o >>= 1) v += __shfl_xor_sync(0xffffffffu, v, o);
    __shared__ float s4[4];
    if ((tid & 31) == 0) s4[tid >> 5] = v;
    __syncthreads();
    if (tid == 0) g_cedge = s4[0] + s4[1] + s4[2] + s4[3];
}

// warp per node: h = x @ w_gat, a_src/a_dst dots
__global__ __launch_bounds__(256) void k_node_transform(
    const float* __restrict__ x, const float* __restrict__ w_gat,
    const float* __restrict__ att_src, const float* __restrict__ att_dst) {
    int n = blockIdx.x * 8 + (threadIdx.x >> 5);
    if (n >= NN) return;
    int lane = threadIdx.x & 31;
    float xr[DIN];
#pragma unroll
    for (int k = 0; k < DIN; k++) xr[k] = x[n * DIN + k];
    float asum = 0.f, dsum = 0.f;
#pragma unroll
    for (int c = 0; c < 4; c++) {
        int j = lane + 32 * c;
        float hj = 0.f;
#pragma unroll
        for (int k = 0; k < DIN; k++) hj += xr[k] * w_gat[k * HID + j];
        g_h[(size_t)n * HID + j] = hj;
        asum += hj * att_src[j];
        dsum += hj * att_dst[j];
    }
#pragma unroll
    for (int o = 16; o > 0; o >>= 1) {
        asum += __shfl_xor_sync(0xffffffffu, asum, o);
        dsum += __shfl_xor_sync(0xffffffffu, dsum, o);
    }
    if (lane == 0) { g_asrc[n] = asum; g_adst[n] = dsum; }
}

__global__ void k_count() {
    int e = blockIdx.x * blockDim.x + threadIdx.x;
    if (e < EE) atomicAdd(&g_counts[g_dst[e]], 1);
}

__global__ void k_scan1() {
    __shared__ int s[SCAN_B];
    int tid = threadIdx.x;
    int gi = blockIdx.x * SCAN_B + tid;
    int v = (gi < NN) ? g_counts[gi] : 0;
    s[tid] = v;
    __syncthreads();
    for (int off = 1; off < SCAN_B; off <<= 1) {
        int t = (tid >= off) ? s[tid - off] : 0;
        __syncthreads();
        s[tid] += t;
        __syncthreads();
    }
    if (gi < NN) g_offsets[gi] = s[tid] - v;
    if (tid == SCAN_B - 1) g_bsum[blockIdx.x] = s[tid];
}

__global__ void k_scan2() {
    int acc = 0;
    for (int b = 0; b < NB; b++) {
        int v = g_bsum[b];
        g_bsum[b] = acc;
        acc += v;
    }
}

__global__ void k_scan3() {
    int tid = threadIdx.x;
    int gi = blockIdx.x * SCAN_B + tid;
    if (gi < NN) {
        int o = g_offsets[gi] + g_bsum[blockIdx.x];
        g_offsets[gi] = o;
        g_cursor[gi]  = o;
        g_ind[gi]     = (g_counts[gi] > 0) ? 1.f : 0.f;
    }
    if (gi == 0) g_offsets[NN] = EE;
}

__global__ void k_scatter(const float* __restrict__ ew) {
    int e = blockIdx.x * blockDim.x + threadIdx.x;
    if (e < EE) {
        int pos = atomicAdd(&g_cursor[g_dst[e]], 1);
        g_eid [pos] = e;
        g_srcp[pos] = g_src[e];
        g_ewp [pos] = ew[e];
    }
}

// block per dst node: segment softmax + GAT aggregation (all edge reads coalesced)
__global__ __launch_bounds__(128) void k_gat(const float* __restrict__ b_gat) {
    int n = blockIdx.x;
    int tid = threadIdx.x;
    int off = g_offsets[n];
    int deg = g_offsets[n + 1] - off;
    float adst_n = g_adst[n];
    float c = g_cedge;

    __shared__ int   s_src[128];
    __shared__ float s_a[128];

    // pass A: logits (store to g_alphap, coalesced)
    float lmax = -3.0e38f;
    for (int i = tid; i < deg; i += 128) {
        float l = g_asrc[g_srcp[off + i]] + adst_n + c * g_ewp[off + i];
        l = (l > 0.f) ? l : SLOPE * l;
        g_alphap[off + i] = l;
        lmax = fmaxf(lmax, l);
    }
    float m = bred_max128(lmax);

    // pass B: exp + denom
    float lsum = 0.f;
    for (int i = tid; i < deg; i += 128) {
        float ev = __expf(g_alphap[off + i] - m);
        g_alphap[off + i] = ev;
        lsum += ev;
    }
    float denom = bred_sum128(lsum);
    float invd = 1.f / fmaxf(denom, 1e-16f);

    // pass C: normalize + aggregate
    float acc = 0.f;
    for (int chunk = 0; chunk < deg; chunk += 128) {
        int i = chunk + tid;
        __syncthreads();
        if (i < deg) {
            s_src[tid] = g_srcp[off + i];
            float a = g_alphap[off + i] * invd;
            g_alphap[off + i] = a;
            s_a[tid] = a;
        }
        __syncthreads();
        int cend = min(128, deg - chunk);
#pragma unroll 8
        for (int k = 0; k < cend; k++)
            acc += s_a[k] * g_h[(size_t)s_src[k] * HID + tid];
    }
    float hg = acc + b_gat[tid];
    g_h1[(size_t)n * HID + tid] = (hg > 0.f) ? hg : 0.f;
}

// hx = h1 @ w_gcn : 32 nodes per block, packed f32x2 FMA
__global__ __launch_bounds__(256) void k_gemm(const float* __restrict__ w_gcn) {
    int n0 = blockIdx.x * 32;
    __shared__ float sh[32][HID];
    for (int i = threadIdx.x; i < 32 * HID; i += 256)
        sh[i >> 7][i & 127] = g_h1[(size_t)n0 * HID + i];
    __syncthreads();

    int cg = threadIdx.x & 31;   // col group: cols 4*cg .. 4*cg+3
    int ng = threadIdx.x >> 5;   // node group: nodes ng*4 .. ng*4+3
    int jc = cg * 4;
    unsigned long long acc[4][2];
    unsigned long long z = pack2(0.f, 0.f);
#pragma unroll
    for (int r = 0; r < 4; r++) { acc[r][0] = z; acc[r][1] = z; }

#pragma unroll 4
    for (int k = 0; k < HID; k++) {
        ulonglong2 wv = *(const ulonglong2*)&w_gcn[k * HID + jc];  // (w0,w1),(w2,w3)
#pragma unroll
        for (int r = 0; r < 4; r++) {
            float a = sh[ng * 4 + r][k];
            unsigned long long aa = pack2(a, a);
            acc[r][0] = fma2(aa, wv.x, acc[r][0]);
            acc[r][1] = fma2(aa, wv.y, acc[r][1]);
        }
    }
#pragma unroll
    for (int r = 0; r < 4; r++) {
        float4 o;
        unpack2(acc[r][0], o.x, o.y);
        unpack2(acc[r][1], o.z, o.w);
        *(float4*)&g_hx[(size_t)(n0 + ng * 4 + r) * HID + jc] = o;
    }
}

// block per dst node: GCN aggregation + relu + output head
__global__ __launch_bounds__(128) void k_gcn_out(
    const float* __restrict__ b_gcn, const float* __restrict__ w_out,
    const float* __restrict__ b_out, float* __restrict__ out) {
    int n = blockIdx.x;
    int tid = threadIdx.x;
    int off = g_offsets[n];
    int deg = g_offsets[n + 1] - off;

    __shared__ int   s_src[128];
    __shared__ float s_w[128];

    float acc = 0.f;
    for (int chunk = 0; chunk < deg; chunk += 128) {
        int i = chunk + tid;
        __syncthreads();
        if (i < deg) {
            int s = g_srcp[off + i];
            s_src[tid] = s;
            // norm = dinv[src]*alpha*dinv[dst]; sum(alpha)=1 per non-empty dst
            s_w[tid] = g_alphap[off + i] * g_ind[s];
        }
        __syncthreads();
        int cend = min(128, deg - chunk);
#pragma unroll 8
        for (int k = 0; k < cend; k++)
            acc += s_w[k] * g_hx[(size_t)s_src[k] * HID + tid];
    }
    float h2 = acc + b_gcn[tid];
    h2 = (h2 > 0.f) ? h2 : 0.f;

    float v0 = h2 * w_out[tid * 2 + 0];
    float v1 = h2 * w_out[tid * 2 + 1];
#pragma unroll
    for (int o = 16; o > 0; o >>= 1) {
        v0 += __shfl_xor_sync(0xffffffffu, v0, o);
        v1 += __shfl_xor_sync(0xffffffffu, v1, o);
    }
    __shared__ float s0[4], s1[4];
    if ((tid & 31) == 0) { s0[tid >> 5] = v0; s1[tid >> 5] = v1; }
    __syncthreads();
    if (tid == 0) {
        out[n * 2 + 0] = s0[0] + s0[1] + s0[2] + s0[3] + b_out[0];
        out[n * 2 + 1] = s1[0] + s1[1] + s1[2] + s1[3] + b_out[1];
    }
}

__global__ void k_copy_ei_f(float* __restrict__ dst) {
    int i = blockIdx.x * blockDim.x + threadIdx.x;
    if (i < EE) dst[i] = (float)g_src[i];
    else if (i < 2 * EE) dst[i] = (float)g_dst[i - EE];
}

// alpha back to original edge order
__global__ void k_copy_alpha(float* __restrict__ dst) {
    int i = blockIdx.x * blockDim.x + threadIdx.x;
    if (i < EE) dst[g_eid[i]] = g_alphap[i];
}

// ---------------- launch ----------------
extern "C" void kernel_launch(void* const* d_in, const int* in_sizes, int n_in,
                              void* d_out, int out_size) {
    int iei, iew, iwg, ias, iad, iwe, iae, ibg, iwgcn, ibgcn, iwo, ibo;
    if (in_sizes[1] == 2 * EE) {
        iei = 1; iew = 2; iwg = 3; ias = 4; iad = 5; iwe = 6; iae = 7;
        ibg = 8; iwgcn = 9; ibgcn = 10; iwo = 11; ibo = 12;
    } else {
        iew = 1; iwg = 2; ias = 3; iad = 4; iwe = 5; iae = 6; ibg = 7;
        iwgcn = 8; ibgcn = 9; iwo = 10; ibo = 11; iei = 12;
    }

    const float* x        = (const float*)d_in[0];
    const void*  ei       = d_in[iei];
    const float* ew       = (const float*)d_in[iew];
    const float* w_gat    = (const float*)d_in[iwg];
    const float* att_src  = (const float*)d_in[ias];
    const float* att_dst  = (const float*)d_in[iad];
    const float* w_edge   = (const float*)d_in[iwe];
    const float* att_edge = (const float*)d_in[iae];
    const float* b_gat    = (const float*)d_in[ibg];
    const float* w_gcn    = (const float*)d_in[iwgcn];
    const float* b_gcn    = (const float*)d_in[ibgcn];
    const float* w_out    = (const float*)d_in[iwo];
    const float* b_out    = (const float*)d_in[ibo];
    float*       out      = (float*)d_out;

    k_detect<<<1, 256>>>((const int*)ei);
    k_convert<<<(EE + 255) / 256, 256>>>(ei);
    k_init_counts<<<(NN + 255) / 256, 256>>>();
    k_calc_cedge<<<1, 128>>>(w_edge, att_edge);
    k_node_transform<<<NN / 8, 256>>>(x, w_gat, att_src, att_dst);
    k_count<<<(EE + 255) / 256, 256>>>();
    k_scan1<<<NB, SCAN_B>>>();
    k_scan2<<<1, 1>>>();
    k_scan3<<<NB, SCAN_B>>>();
    k_scatter<<<(EE + 255) / 256, 256>>>(ew);
    k_gat<<<NN, 128>>>(b_gat);
    k_gemm<<<NN / 32, 256>>>(w_gcn);
    k_gcn_out<<<NN, 128>>>(b_gcn, w_out, b_out, out);

    int rem = out_size - NN * OUTD;
    if (rem == EE) {
        k_copy_alpha<<<(EE + 255) / 256, 256>>>(out + NN * OUTD);
    } else if (rem == 3 * EE) {
        k_copy_ei_f<<<(2 * EE + 255) / 256, 256>>>(out + NN * OUTD);
        k_copy_alpha<<<(EE + 255) / 256, 256>>>(out + NN * OUTD + 2 * EE);
    }
}

// round 5
// speedup vs baseline: 1.8389x; 1.2647x over previous
#include <cuda_runtime.h>
#include <math.h>

#define NN   100000
#define EE   1600000
#define HID  128
#define DIN  6
#define OUTD 2
#define SLOPE 0.2f

#define SCAN_B 1024
#define NB ((NN + SCAN_B - 1) / SCAN_B)   // 98
#define FULLM 0xffffffffu

// ---------------- device scratch ----------------
__device__ float g_h    [NN * HID];
__device__ float g_h1   [NN * HID];
__device__ float g_hx   [NN * HID];
__device__ float g_asrc [NN];
__device__ float g_adst [NN];
__device__ float g_ind  [NN];         // 1.0 if node has incoming edges
__device__ float g_alphap[EE];        // exp(logit) -> normalized alpha, CSR order
__device__ int   g_src  [EE];
__device__ int   g_dst  [EE];
__device__ int   g_srcp [EE];         // src index in CSR order
__device__ int   g_eid  [EE];         // original edge id per CSR pos
__device__ int   g_counts [NN];
__device__ int   g_offsets[NN + 1];
__device__ int   g_cursor [NN];
__device__ int   g_bsum   [NB];
__device__ float g_cedge;
__device__ int   g_is64;

// ---------------- f32x2 helpers ----------------
__device__ __forceinline__ unsigned long long pack2(float a, float b) {
    unsigned long long r;
    asm("mov.b64 %0, {%1, %2};" : "=l"(r) : "f"(a), "f"(b));
    return r;
}
__device__ __forceinline__ void unpack2(unsigned long long v, float& a, float& b) {
    asm("mov.b64 {%0, %1}, %2;" : "=f"(a), "=f"(b) : "l"(v));
}
__device__ __forceinline__ unsigned long long fma2(
    unsigned long long a, unsigned long long b, unsigned long long c) {
    unsigned long long d;
    asm("fma.rn.f32x2 %0, %1, %2, %3;" : "=l"(d) : "l"(a), "l"(b), "l"(c));
    return d;
}

// ---------------- dtype probe + convert ----------------
__global__ void k_detect(const int* __restrict__ ei32) {
    __shared__ int nz;
    if (threadIdx.x == 0) nz = 0;
    __syncthreads();
    int found = 0;
    for (int i = threadIdx.x; i < 4096; i += blockDim.x)
        if (ei32[2 * i + 1] != 0) found = 1;
    if (found) atomicAdd(&nz, 1);
    __syncthreads();
    if (threadIdx.x == 0) g_is64 = (nz == 0) ? 1 : 0;
}

__global__ void k_init_counts() {
    int i = blockIdx.x * blockDim.x + threadIdx.x;
    if (i < NN) g_counts[i] = 0;
}

// convert + degree histogram fused
__global__ void k_convert(const void* __restrict__ ei) {
    int e = blockIdx.x * blockDim.x + threadIdx.x;
    if (e >= EE) return;
    int s, d;
    if (g_is64) {
        const long long* p = (const long long*)ei;
        s = (int)p[e];
        d = (int)p[EE + e];
    } else {
        const int* p = (const int*)ei;
        s = p[e];
        d = p[EE + e];
    }
    g_src[e] = s;
    g_dst[e] = d;
    atomicAdd(&g_counts[d], 1);
}

__global__ void k_calc_cedge(const float* __restrict__ w_edge,
                             const float* __restrict__ att_edge) {
    int tid = threadIdx.x;
    float v = w_edge[tid] * att_edge[tid];
#pragma unroll
    for (int o = 16; o > 0; o >>= 1) v += __shfl_xor_sync(FULLM, v, o);
    __shared__ float s4[4];
    if ((tid & 31) == 0) s4[tid >> 5] = v;
    __syncthreads();
    if (tid == 0) g_cedge = s4[0] + s4[1] + s4[2] + s4[3];
}

// warp per node: h = x @ w_gat, a_src/a_dst dots
__global__ __launch_bounds__(256) void k_node_transform(
    const float* __restrict__ x, const float* __restrict__ w_gat,
    const float* __restrict__ att_src, const float* __restrict__ att_dst) {
    int n = blockIdx.x * 8 + (threadIdx.x >> 5);
    if (n >= NN) return;
    int lane = threadIdx.x & 31;
    float xr[DIN];
#pragma unroll
    for (int k = 0; k < DIN; k++) xr[k] = x[n * DIN + k];
    float asum = 0.f, dsum = 0.f;
#pragma unroll
    for (int c = 0; c < 4; c++) {
        int j = lane + 32 * c;
        float hj = 0.f;
#pragma unroll
        for (int k = 0; k < DIN; k++) hj += xr[k] * w_gat[k * HID + j];
        g_h[(size_t)n * HID + j] = hj;
        asum += hj * att_src[j];
        dsum += hj * att_dst[j];
    }
#pragma unroll
    for (int o = 16; o > 0; o >>= 1) {
        asum += __shfl_xor_sync(FULLM, asum, o);
        dsum += __shfl_xor_sync(FULLM, dsum, o);
    }
    if (lane == 0) { g_asrc[n] = asum; g_adst[n] = dsum; }
}

__global__ void k_scan1() {
    __shared__ int s[SCAN_B];
    int tid = threadIdx.x;
    int gi = blockIdx.x * SCAN_B + tid;
    int v = (gi < NN) ? g_counts[gi] : 0;
    s[tid] = v;
    __syncthreads();
    for (int off = 1; off < SCAN_B; off <<= 1) {
        int t = (tid >= off) ? s[tid - off] : 0;
        __syncthreads();
        s[tid] += t;
        __syncthreads();
    }
    if (gi < NN) g_offsets[gi] = s[tid] - v;
    if (tid == SCAN_B - 1) g_bsum[blockIdx.x] = s[tid];
}

__global__ void k_scan2() {
    int acc = 0;
    for (int b = 0; b < NB; b++) {
        int v = g_bsum[b];
        g_bsum[b] = acc;
        acc += v;
    }
}

__global__ void k_scan3() {
    int tid = threadIdx.x;
    int gi = blockIdx.x * SCAN_B + tid;
    if (gi < NN) {
        int o = g_offsets[gi] + g_bsum[blockIdx.x];
        g_offsets[gi] = o;
        g_cursor[gi]  = o;
        g_ind[gi]     = (g_counts[gi] > 0) ? 1.f : 0.f;
    }
    if (gi == 0) g_offsets[NN] = EE;
}

// scatter + fused logit/exp (max-subtraction skipped: logits are O(1),
// alpha = e^l / sum e^l is identical without it)
__global__ void k_scatter(const float* __restrict__ ew) {
    int e = blockIdx.x * blockDim.x + threadIdx.x;
    if (e >= EE) return;
    int s = g_src[e];
    int d = g_dst[e];
    float l = g_asrc[s] + g_adst[d] + g_cedge * ew[e];
    l = (l > 0.f) ? l : SLOPE * l;
    float ev = __expf(l);
    int pos = atomicAdd(&g_cursor[d], 1);
    g_srcp [pos] = s;
    g_alphap[pos] = ev;
    g_eid  [pos] = e;
}

// warp per dst node: denom + normalize + GAT aggregation (no smem, no block sync)
__global__ __launch_bounds__(256) void k_gat(const float* __restrict__ b_gat) {
    int n = blockIdx.x * 8 + (threadIdx.x >> 5);
    if (n >= NN) return;
    int lane = threadIdx.x & 31;
    int off = g_offsets[n];
    int deg = g_offsets[n + 1] - off;

    float lsum = 0.f;
    for (int i = lane; i < deg; i += 32) lsum += g_alphap[off + i];
#pragma unroll
    for (int o = 16; o > 0; o >>= 1) lsum += __shfl_xor_sync(FULLM, lsum, o);
    float invd = 1.f / fmaxf(lsum, 1e-16f);

    unsigned long long acc0 = pack2(0.f, 0.f), acc1 = acc0;
    for (int base = 0; base < deg; base += 32) {
        int i = base + lane;
        int msrc = 0; float ma = 0.f;
        if (i < deg) {
            msrc = g_srcp[off + i];
            ma = g_alphap[off + i] * invd;
            g_alphap[off + i] = ma;        // final normalized alpha
        }
        int cnt = min(32, deg - base);
        for (int k = 0; k < cnt; k++) {
            int   s = __shfl_sync(FULLM, msrc, k);
            float a = __shfl_sync(FULLM, ma, k);
            ulonglong2 hv = *(const ulonglong2*)&g_h[(size_t)s * HID + lane * 4];
            unsigned long long aa = pack2(a, a);
            acc0 = fma2(aa, hv.x, acc0);
            acc1 = fma2(aa, hv.y, acc1);
        }
    }
    float4 b4 = *(const float4*)&b_gat[lane * 4];
    float4 r;
    unpack2(acc0, r.x, r.y);
    unpack2(acc1, r.z, r.w);
    r.x = fmaxf(r.x + b4.x, 0.f);
    r.y = fmaxf(r.y + b4.y, 0.f);
    r.z = fmaxf(r.z + b4.z, 0.f);
    r.w = fmaxf(r.w + b4.w, 0.f);
    *(float4*)&g_h1[(size_t)n * HID + lane * 4] = r;
}

// hx = ind[row] * (h1 @ w_gcn) : 32 nodes per block, packed f32x2 FMA
__global__ __launch_bounds__(256) void k_gemm(const float* __restrict__ w_gcn) {
    int n0 = blockIdx.x * 32;
    __shared__ float sh[32][HID];
    for (int i = threadIdx.x; i < 32 * HID; i += 256)
        sh[i >> 7][i & 127] = g_h1[(size_t)n0 * HID + i];
    __syncthreads();

    int cg = threadIdx.x & 31;
    int ng = threadIdx.x >> 5;
    int jc = cg * 4;
    unsigned long long acc[4][2];
    unsigned long long z = pack2(0.f, 0.f);
#pragma unroll
    for (int r = 0; r < 4; r++) { acc[r][0] = z; acc[r][1] = z; }

#pragma unroll 4
    for (int k = 0; k < HID; k++) {
        ulonglong2 wv = *(const ulonglong2*)&w_gcn[k * HID + jc];
#pragma unroll
        for (int r = 0; r < 4; r++) {
            float a = sh[ng * 4 + r][k];
            unsigned long long aa = pack2(a, a);
            acc[r][0] = fma2(aa, wv.x, acc[r][0]);
            acc[r][1] = fma2(aa, wv.y, acc[r][1]);
        }
    }
#pragma unroll
    for (int r = 0; r < 4; r++) {
        int row = n0 + ng * 4 + r;
        float ind = g_ind[row];            // fold dinv[src] indicator into hx
        float4 o;
        unpack2(acc[r][0], o.x, o.y);
        unpack2(acc[r][1], o.z, o.w);
        o.x *= ind; o.y *= ind; o.z *= ind; o.w *= ind;
        *(float4*)&g_hx[(size_t)row * HID + jc] = o;
    }
}

// warp per dst node: GCN aggregation + relu + output head
__global__ __launch_bounds__(256) void k_gcn_out(
    const float* __restrict__ b_gcn, const float* __restrict__ w_out,
    const float* __restrict__ b_out, float* __restrict__ out) {
    int n = blockIdx.x * 8 + (threadIdx.x >> 5);
    if (n >= NN) return;
    int lane = threadIdx.x & 31;
    int off = g_offsets[n];
    int deg = g_offsets[n + 1] - off;

    unsigned long long acc0 = pack2(0.f, 0.f), acc1 = acc0;
    for (int base = 0; base < deg; base += 32) {
        int i = base + lane;
        int msrc = 0; float ma = 0.f;
        if (i < deg) {
            msrc = g_srcp[off + i];
            ma = g_alphap[off + i];        // normalized alpha; ind folded into hx
        }
        int cnt = min(32, deg - base);
        for (int k = 0; k < cnt; k++) {
            int   s = __shfl_sync(FULLM, msrc, k);
            float a = __shfl_sync(FULLM, ma, k);
            ulonglong2 hv = *(const ulonglong2*)&g_hx[(size_t)s * HID + lane * 4];
            unsigned long long aa = pack2(a, a);
            acc0 = fma2(aa, hv.x, acc0);
            acc1 = fma2(aa, hv.y, acc1);
        }
    }
    float4 b4 = *(const float4*)&b_gcn[lane * 4];
    float4 h2;
    unpack2(acc0, h2.x, h2.y);
    unpack2(acc1, h2.z, h2.w);
    h2.x = fmaxf(h2.x + b4.x, 0.f);
    h2.y = fmaxf(h2.y + b4.y, 0.f);
    h2.z = fmaxf(h2.z + b4.z, 0.f);
    h2.w = fmaxf(h2.w + b4.w, 0.f);

    // head: out[n,:] = h2 @ w_out + b_out, w_out row-major [HID,2]
    int jc = lane * 4;
    float v0 = h2.x * w_out[(jc + 0) * 2] + h2.y * w_out[(jc + 1) * 2]
             + h2.z * w_out[(jc + 2) * 2] + h2.w * w_out[(jc + 3) * 2];
    float v1 = h2.x * w_out[(jc + 0) * 2 + 1] + h2.y * w_out[(jc + 1) * 2 + 1]
             + h2.z * w_out[(jc + 2) * 2 + 1] + h2.w * w_out[(jc + 3) * 2 + 1];
#pragma unroll
    for (int o = 16; o > 0; o >>= 1) {
        v0 += __shfl_xor_sync(FULLM, v0, o);
        v1 += __shfl_xor_sync(FULLM, v1, o);
    }
    if (lane == 0) {
        out[n * 2 + 0] = v0 + b_out[0];
        out[n * 2 + 1] = v1 + b_out[1];
    }
}

__global__ void k_copy_ei_f(float* __restrict__ dst) {
    int i = blockIdx.x * blockDim.x + threadIdx.x;
    if (i < EE) dst[i] = (float)g_src[i];
    else if (i < 2 * EE) dst[i] = (float)g_dst[i - EE];
}

__global__ void k_copy_alpha(float* __restrict__ dst) {
    int i = blockIdx.x * blockDim.x + threadIdx.x;
    if (i < EE) dst[g_eid[i]] = g_alphap[i];
}

// ---------------- launch ----------------
extern "C" void kernel_launch(void* const* d_in, const int* in_sizes, int n_in,
                              void* d_out, int out_size) {
    int iei, iew, iwg, ias, iad, iwe, iae, ibg, iwgcn, ibgcn, iwo, ibo;
    if (in_sizes[1] == 2 * EE) {
        iei = 1; iew = 2; iwg = 3; ias = 4; iad = 5; iwe = 6; iae = 7;
        ibg = 8; iwgcn = 9; ibgcn = 10; iwo = 11; ibo = 12;
    } else {
        iew = 1; iwg = 2; ias = 3; iad = 4; iwe = 5; iae = 6; ibg = 7;
        iwgcn = 8; ibgcn = 9; iwo = 10; ibo = 11; iei = 12;
    }

    const float* x        = (const float*)d_in[0];
    const void*  ei       = d_in[iei];
    const float* ew       = (const float*)d_in[iew];
    const float* w_gat    = (const float*)d_in[iwg];
    const float* att_src  = (const float*)d_in[ias];
    const float* att_dst  = (const float*)d_in[iad];
    const float* w_edge   = (const float*)d_in[iwe];
    const float* att_edge = (const float*)d_in[iae];
    const float* b_gat    = (const float*)d_in[ibg];
    const float* w_gcn    = (const float*)d_in[iwgcn];
    const float* b_gcn    = (const float*)d_in[ibgcn];
    const float* w_out    = (const float*)d_in[iwo];
    const float* b_out    = (const float*)d_in[ibo];
    float*       out      = (float*)d_out;

    k_detect<<<1, 256>>>((const int*)ei);
    k_init_counts<<<(NN + 255) / 256, 256>>>();
    k_convert<<<(EE + 255) / 256, 256>>>(ei);
    k_calc_cedge<<<1, 128>>>(w_edge, att_edge);
    k_node_transform<<<NN / 8, 256>>>(x, w_gat, att_src, att_dst);
    k_scan1<<<NB, SCAN_B>>>();
    k_scan2<<<1, 1>>>();
    k_scan3<<<NB, SCAN_B>>>();
    k_scatter<<<(EE + 255) / 256, 256>>>(ew);
    k_gat<<<NN / 8, 256>>>(b_gat);
    k_gemm<<<NN / 32, 256>>>(w_gcn);
    k_gcn_out<<<NN / 8, 256>>>(b_gcn, w_out, b_out, out);

    int rem = out_size - NN * OUTD;
    if (rem == EE) {
        k_copy_alpha<<<(EE + 255) / 256, 256>>>(out + NN * OUTD);
    } else if (rem == 3 * EE) {
        k_copy_ei_f<<<(2 * EE + 255) / 256, 256>>>(out + NN * OUTD);
        k_copy_alpha<<<(EE + 255) / 256, 256>>>(out + NN * OUTD + 2 * EE);
    }
}

// round 6
// speedup vs baseline: 1.9400x; 1.0550x over previous
#include <cuda_runtime.h>
#include <math.h>

#define NN   100000
#define EE   1600000
#define HID  128
#define DIN  6
#define OUTD 2
#define SLOPE 0.2f

#define SCAN_B 1024
#define NB ((NN + SCAN_B - 1) / SCAN_B)   // 98
#define FULLM 0xffffffffu

// ---------------- device scratch ----------------
__device__ float g_h    [NN * HID];
__device__ float g_h1   [NN * HID];
__device__ float g_hx   [NN * HID];
__device__ float g_asrc [NN];
__device__ float g_adst [NN];
__device__ float g_ind  [NN];
__device__ float g_alphap[EE];        // exp(logit) -> normalized alpha, CSR order
__device__ int   g_src  [EE];
__device__ int   g_dst  [EE];
__device__ int   g_srcp [EE];
__device__ int   g_eid  [EE];
__device__ int   g_counts [NN];
__device__ int   g_offsets[NN + 1];
__device__ int   g_cursor [NN];
__device__ int   g_bsum   [NB];
__device__ float g_cedge;
__device__ int   g_is64;

// ---------------- f32x2 helpers ----------------
__device__ __forceinline__ unsigned long long pack2(float a, float b) {
    unsigned long long r;
    asm("mov.b64 %0, {%1, %2};" : "=l"(r) : "f"(a), "f"(b));
    return r;
}
__device__ __forceinline__ void unpack2(unsigned long long v, float& a, float& b) {
    asm("mov.b64 {%0, %1}, %2;" : "=f"(a), "=f"(b) : "l"(v));
}
__device__ __forceinline__ unsigned long long fma2(
    unsigned long long a, unsigned long long b, unsigned long long c) {
    unsigned long long d;
    asm("fma.rn.f32x2 %0, %1, %2, %3;" : "=l"(d) : "l"(a), "l"(b), "l"(c));
    return d;
}

// ---------------- fused pre-pass: zero counts, dtype probe, cedge ----------------
__global__ void k_pre(const int* __restrict__ ei32,
                      const float* __restrict__ w_edge,
                      const float* __restrict__ att_edge) {
    int i = blockIdx.x * blockDim.x + threadIdx.x;
    if (i < NN) g_counts[i] = 0;

    if (blockIdx.x == 0) {
        // dtype probe: int64 buffer (values < 2^31) -> all odd words zero
        __shared__ int nz;
        if (threadIdx.x == 0) nz = 0;
        __syncthreads();
        int found = 0;
        for (int t = threadIdx.x; t < 4096; t += blockDim.x)
            if (ei32[2 * t + 1] != 0) found = 1;
        if (found) atomicAdd(&nz, 1);
        __syncthreads();
        if (threadIdx.x == 0) g_is64 = (nz == 0) ? 1 : 0;
    } else if (blockIdx.x == 1 && threadIdx.x < 128) {
        float v = w_edge[threadIdx.x] * att_edge[threadIdx.x];
#pragma unroll
        for (int o = 16; o > 0; o >>= 1) v += __shfl_xor_sync(FULLM, v, o);
        __shared__ float s4[4];
        if ((threadIdx.x & 31) == 0) s4[threadIdx.x >> 5] = v;
        __syncthreads();
        if (threadIdx.x == 0) g_cedge = s4[0] + s4[1] + s4[2] + s4[3];
    }
}

// convert + degree histogram fused
__global__ void k_convert(const void* __restrict__ ei) {
    int e = blockIdx.x * blockDim.x + threadIdx.x;
    if (e >= EE) return;
    int s, d;
    if (g_is64) {
        const long long* p = (const long long*)ei;
        s = (int)p[e];
        d = (int)p[EE + e];
    } else {
        const int* p = (const int*)ei;
        s = p[e];
        d = p[EE + e];
    }
    g_src[e] = s;
    g_dst[e] = d;
    atomicAdd(&g_counts[d], 1);
}

// warp per node: h = x @ w_gat, a_src/a_dst dots
__global__ __launch_bounds__(256) void k_node_transform(
    const float* __restrict__ x, const float* __restrict__ w_gat,
    const float* __restrict__ att_src, const float* __restrict__ att_dst) {
    int n = blockIdx.x * 8 + (threadIdx.x >> 5);
    if (n >= NN) return;
    int lane = threadIdx.x & 31;
    float xr[DIN];
#pragma unroll
    for (int k = 0; k < DIN; k++) xr[k] = x[n * DIN + k];
    float asum = 0.f, dsum = 0.f;
#pragma unroll
    for (int c = 0; c < 4; c++) {
        int j = lane + 32 * c;
        float hj = 0.f;
#pragma unroll
        for (int k = 0; k < DIN; k++) hj += xr[k] * w_gat[k * HID + j];
        g_h[(size_t)n * HID + j] = hj;
        asum += hj * att_src[j];
        dsum += hj * att_dst[j];
    }
#pragma unroll
    for (int o = 16; o > 0; o >>= 1) {
        asum += __shfl_xor_sync(FULLM, asum, o);
        dsum += __shfl_xor_sync(FULLM, dsum, o);
    }
    if (lane == 0) { g_asrc[n] = asum; g_adst[n] = dsum; }
}

__global__ void k_scan1() {
    __shared__ int s[SCAN_B];
    int tid = threadIdx.x;
    int gi = blockIdx.x * SCAN_B + tid;
    int v = (gi < NN) ? g_counts[gi] : 0;
    s[tid] = v;
    __syncthreads();
    for (int off = 1; off < SCAN_B; off <<= 1) {
        int t = (tid >= off) ? s[tid - off] : 0;
        __syncthreads();
        s[tid] += t;
        __syncthreads();
    }
    if (gi < NN) g_offsets[gi] = s[tid] - v;
    if (tid == SCAN_B - 1) g_bsum[blockIdx.x] = s[tid];
}

// scan3 with scan2 folded in: per-block prefix of g_bsum computed locally
__global__ void k_scan3() {
    __shared__ int spre;
    int tid = threadIdx.x;
    if (tid == 0) spre = 0;
    __syncthreads();
    if (tid < NB && tid < blockIdx.x) atomicAdd(&spre, g_bsum[tid]);
    __syncthreads();
    int pre = spre;
    int gi = blockIdx.x * SCAN_B + tid;
    if (gi < NN) {
        int o = g_offsets[gi] + pre;
        g_offsets[gi] = o;
        g_cursor[gi]  = o;
        g_ind[gi]     = (g_counts[gi] > 0) ? 1.f : 0.f;
    }
    if (gi == 0) g_offsets[NN] = EE;
}

// scatter + fused logit/exp (logits are O(1); softmax max-shift unnecessary)
__global__ void k_scatter(const float* __restrict__ ew) {
    int e = blockIdx.x * blockDim.x + threadIdx.x;
    if (e >= EE) return;
    int s = g_src[e];
    int d = g_dst[e];
    float l = g_asrc[s] + g_adst[d] + g_cedge * ew[e];
    l = (l > 0.f) ? l : SLOPE * l;
    float ev = __expf(l);
    int pos = atomicAdd(&g_cursor[d], 1);
    g_srcp [pos] = s;
    g_alphap[pos] = ev;
    g_eid  [pos] = e;
}

// warp per dst node: denom + normalize + GAT aggregation (2-edge unrolled, MLP=2)
__global__ __launch_bounds__(256) void k_gat(const float* __restrict__ b_gat) {
    int n = blockIdx.x * 8 + (threadIdx.x >> 5);
    if (n >= NN) return;
    int lane = threadIdx.x & 31;
    int off = g_offsets[n];
    int deg = g_offsets[n + 1] - off;

    float lsum = 0.f;
    for (int i = lane; i < deg; i += 32) lsum += g_alphap[off + i];
#pragma unroll
    for (int o = 16; o > 0; o >>= 1) lsum += __shfl_xor_sync(FULLM, lsum, o);
    float invd = 1.f / fmaxf(lsum, 1e-16f);

    unsigned long long acc0 = pack2(0.f, 0.f), acc1 = acc0;
    for (int base = 0; base < deg; base += 32) {
        int i = base + lane;
        int msrc = 0; float ma = 0.f;
        if (i < deg) {
            msrc = g_srcp[off + i];
            ma = g_alphap[off + i] * invd;
            g_alphap[off + i] = ma;        // final normalized alpha
        }
        int cnt = min(32, deg - base);
        int k = 0;
        for (; k + 2 <= cnt; k += 2) {
            int   s0 = __shfl_sync(FULLM, msrc, k);
            float a0 = __shfl_sync(FULLM, ma,   k);
            int   s1 = __shfl_sync(FULLM, msrc, k + 1);
            float a1 = __shfl_sync(FULLM, ma,   k + 1);
            ulonglong2 h0 = *(const ulonglong2*)&g_h[(size_t)s0 * HID + lane * 4];
            ulonglong2 h1 = *(const ulonglong2*)&g_h[(size_t)s1 * HID + lane * 4];
            unsigned long long p0 = pack2(a0, a0), p1 = pack2(a1, a1);
            acc0 = fma2(p0, h0.x, acc0);
            acc1 = fma2(p0, h0.y, acc1);
            acc0 = fma2(p1, h1.x, acc0);
            acc1 = fma2(p1, h1.y, acc1);
        }
        if (k < cnt) {
            int   s0 = __shfl_sync(FULLM, msrc, k);
            float a0 = __shfl_sync(FULLM, ma,   k);
            ulonglong2 h0 = *(const ulonglong2*)&g_h[(size_t)s0 * HID + lane * 4];
            unsigned long long p0 = pack2(a0, a0);
            acc0 = fma2(p0, h0.x, acc0);
            acc1 = fma2(p0, h0.y, acc1);
        }
    }
    float4 b4 = *(const float4*)&b_gat[lane * 4];
    float4 r;
    unpack2(acc0, r.x, r.y);
    unpack2(acc1, r.z, r.w);
    r.x = fmaxf(r.x + b4.x, 0.f);
    r.y = fmaxf(r.y + b4.y, 0.f);
    r.z = fmaxf(r.z + b4.z, 0.f);
    r.w = fmaxf(r.w + b4.w, 0.f);
    *(float4*)&g_h1[(size_t)n * HID + lane * 4] = r;
}

// hx = ind[row] * (h1 @ w_gcn): 32 nodes/block, smem pre-duplicated f32x2 pairs
__global__ __launch_bounds__(256) void k_gemm(const float* __restrict__ w_gcn) {
    int n0 = blockIdx.x * 32;
    __shared__ unsigned long long shd[HID][34];   // [k][node], (a,a) pairs; pad->16B align
    for (int i = threadIdx.x; i < 32 * HID; i += 256) {
        int nn = i >> 7, kk = i & 127;
        float v = g_h1[(size_t)n0 * HID + i];
        shd[kk][nn] = pack2(v, v);
    }
    __syncthreads();

    int cg = threadIdx.x & 31;   // column group: cols 4*cg..4*cg+3
    int ng = threadIdx.x >> 5;   // node group:   rows ng*4..ng*4+3
    int jc = cg * 4;
    unsigned long long z = pack2(0.f, 0.f);
    unsigned long long acc[4][2];
#pragma unroll
    for (int r = 0; r < 4; r++) { acc[r][0] = z; acc[r][1] = z; }

#pragma unroll 4
    for (int k = 0; k < HID; k++) {
        ulonglong2 wv  = *(const ulonglong2*)&w_gcn[k * HID + jc];
        ulonglong2 p01 = *(const ulonglong2*)&shd[k][ng * 4];      // (a0,a0),(a1,a1)
        ulonglong2 p23 = *(const ulonglong2*)&shd[k][ng * 4 + 2];  // (a2,a2),(a3,a3)
        acc[0][0] = fma2(p01.x, wv.x, acc[0][0]);
        acc[0][1] = fma2(p01.x, wv.y, acc[0][1]);
        acc[1][0] = fma2(p01.y, wv.x, acc[1][0]);
        acc[1][1] = fma2(p01.y, wv.y, acc[1][1]);
        acc[2][0] = fma2(p23.x, wv.x, acc[2][0]);
        acc[2][1] = fma2(p23.x, wv.y, acc[2][1]);
        acc[3][0] = fma2(p23.y, wv.x, acc[3][0]);
        acc[3][1] = fma2(p23.y, wv.y, acc[3][1]);
    }
#pragma unroll
    for (int r = 0; r < 4; r++) {
        int row = n0 + ng * 4 + r;
        float ind = g_ind[row];
        float4 o;
        unpack2(acc[r][0], o.x, o.y);
        unpack2(acc[r][1], o.z, o.w);
        o.x *= ind; o.y *= ind; o.z *= ind; o.w *= ind;
        *(float4*)&g_hx[(size_t)row * HID + jc] = o;
    }
}

// warp per dst node: GCN aggregation + relu + output head (2-edge unrolled)
__global__ __launch_bounds__(256) void k_gcn_out(
    const float* __restrict__ b_gcn, const float* __restrict__ w_out,
    const float* __restrict__ b_out, float* __restrict__ out) {
    int n = blockIdx.x * 8 + (threadIdx.x >> 5);
    if (n >= NN) return;
    int lane = threadIdx.x & 31;
    int off = g_offsets[n];
    int deg = g_offsets[n + 1] - off;

    unsigned long long acc0 = pack2(0.f, 0.f), acc1 = acc0;
    for (int base = 0; base < deg; base += 32) {
        int i = base + lane;
        int msrc = 0; float ma = 0.f;
        if (i < deg) {
            msrc = g_srcp[off + i];
            ma = g_alphap[off + i];
        }
        int cnt = min(32, deg - base);
        int k = 0;
        for (; k + 2 <= cnt; k += 2) {
            int   s0 = __shfl_sync(FULLM, msrc, k);
            float a0 = __shfl_sync(FULLM, ma,   k);
            int   s1 = __shfl_sync(FULLM, msrc, k + 1);
            float a1 = __shfl_sync(FULLM, ma,   k + 1);
            ulonglong2 h0 = *(const ulonglong2*)&g_hx[(size_t)s0 * HID + lane * 4];
            ulonglong2 h1 = *(const ulonglong2*)&g_hx[(size_t)s1 * HID + lane * 4];
            unsigned long long p0 = pack2(a0, a0), p1 = pack2(a1, a1);
            acc0 = fma2(p0, h0.x, acc0);
            acc1 = fma2(p0, h0.y, acc1);
            acc0 = fma2(p1, h1.x, acc0);
            acc1 = fma2(p1, h1.y, acc1);
        }
        if (k < cnt) {
            int   s0 = __shfl_sync(FULLM, msrc, k);
            float a0 = __shfl_sync(FULLM, ma,   k);
            ulonglong2 h0 = *(const ulonglong2*)&g_hx[(size_t)s0 * HID + lane * 4];
            unsigned long long p0 = pack2(a0, a0);
            acc0 = fma2(p0, h0.x, acc0);
            acc1 = fma2(p0, h0.y, acc1);
        }
    }
    float4 b4 = *(const float4*)&b_gcn[lane * 4];
    float4 h2;
    unpack2(acc0, h2.x, h2.y);
    unpack2(acc1, h2.z, h2.w);
    h2.x = fmaxf(h2.x + b4.x, 0.f);
    h2.y = fmaxf(h2.y + b4.y, 0.f);
    h2.z = fmaxf(h2.z + b4.z, 0.f);
    h2.w = fmaxf(h2.w + b4.w, 0.f);

    int jc = lane * 4;
    float v0 = h2.x * w_out[(jc + 0) * 2] + h2.y * w_out[(jc + 1) * 2]
             + h2.z * w_out[(jc + 2) * 2] + h2.w * w_out[(jc + 3) * 2];
    float v1 = h2.x * w_out[(jc + 0) * 2 + 1] + h2.y * w_out[(jc + 1) * 2 + 1]
             + h2.z * w_out[(jc + 2) * 2 + 1] + h2.w * w_out[(jc + 3) * 2 + 1];
#pragma unroll
    for (int o = 16; o > 0; o >>= 1) {
        v0 += __shfl_xor_sync(FULLM, v0, o);
        v1 += __shfl_xor_sync(FULLM, v1, o);
    }
    if (lane == 0) {
        out[n * 2 + 0] = v0 + b_out[0];
        out[n * 2 + 1] = v1 + b_out[1];
    }
}

__global__ void k_copy_ei_f(float* __restrict__ dst) {
    int i = blockIdx.x * blockDim.x + threadIdx.x;
    if (i < EE) dst[i] = (float)g_src[i];
    else if (i < 2 * EE) dst[i] = (float)g_dst[i - EE];
}

__global__ void k_copy_alpha(float* __restrict__ dst) {
    int i = blockIdx.x * blockDim.x + threadIdx.x;
    if (i < EE) dst[g_eid[i]] = g_alphap[i];
}

// ---------------- launch ----------------
extern "C" void kernel_launch(void* const* d_in, const int* in_sizes, int n_in,
                              void* d_out, int out_size) {
    int iei, iew, iwg, ias, iad, iwe, iae, ibg, iwgcn, ibgcn, iwo, ibo;
    if (in_sizes[1] == 2 * EE) {
        iei = 1; iew = 2; iwg = 3; ias = 4; iad = 5; iwe = 6; iae = 7;
        ibg = 8; iwgcn = 9; ibgcn = 10; iwo = 11; ibo = 12;
    } else {
        iew = 1; iwg = 2; ias = 3; iad = 4; iwe = 5; iae = 6; ibg = 7;
        iwgcn = 8; ibgcn = 9; iwo = 10; ibo = 11; iei = 12;
    }

    const float* x        = (const float*)d_in[0];
    const void*  ei       = d_in[iei];
    const float* ew       = (const float*)d_in[iew];
    const float* w_gat    = (const float*)d_in[iwg];
    const float* att_src  = (const float*)d_in[ias];
    const float* att_dst  = (const float*)d_in[iad];
    const float* w_edge   = (const float*)d_in[iwe];
    const float* att_edge = (const float*)d_in[iae];
    const float* b_gat    = (const float*)d_in[ibg];
    const float* w_gcn    = (const float*)d_in[iwgcn];
    const float* b_gcn    = (const float*)d_in[ibgcn];
    const float* w_out    = (const float*)d_in[iwo];
    const float* b_out    = (const float*)d_in[ibo];
    float*       out      = (float*)d_out;

    k_pre<<<(NN + 255) / 256, 256>>>((const int*)ei, w_edge, att_edge);
    k_convert<<<(EE + 255) / 256, 256>>>(ei);
    k_node_transform<<<NN / 8, 256>>>(x, w_gat, att_src, att_dst);
    k_scan1<<<NB, SCAN_B>>>();
    k_scan3<<<NB, SCAN_B>>>();
    k_scatter<<<(EE + 255) / 256, 256>>>(ew);
    k_gat<<<NN / 8, 256>>>(b_gat);
    k_gemm<<<NN / 32, 256>>>(w_gcn);
    k_gcn_out<<<NN / 8, 256>>>(b_gcn, w_out, b_out, out);

    int rem = out_size - NN * OUTD;
    if (rem == EE) {
        k_copy_alpha<<<(EE + 255) / 256, 256>>>(out + NN * OUTD);
    } else if (rem == 3 * EE) {
        k_copy_ei_f<<<(2 * EE + 255) / 256, 256>>>(out + NN * OUTD);
        k_copy_alpha<<<(EE + 255) / 256, 256>>>(out + NN * OUTD + 2 * EE);
    }
}

// round 7
// speedup vs baseline: 1.9994x; 1.0306x over previous
#include <cuda_runtime.h>
#include <math.h>

#define NN   100000
#define EE   1600000
#define HID  128
#define DIN  6
#define OUTD 2
#define SLOPE 0.2f

#define SCAN_B 1024
#define NB ((NN + SCAN_B - 1) / SCAN_B)   // 98
#define FULLM 0xffffffffu

// ---------------- device scratch ----------------
__device__ float g_h    [NN * HID];
__device__ float g_h1   [NN * HID];
__device__ float g_hx   [NN * HID];
__device__ float g_asrc [NN];
__device__ float g_adst [NN];
__device__ float g_ind  [NN];
__device__ int4  g_edge [EE];         // {src, alpha_bits, eid, unused} in CSR order
__device__ int   g_counts [NN];
__device__ int   g_offsets[NN + 1];
__device__ int   g_cursor [NN];
__device__ int   g_bsum   [NB];
__device__ float g_cedge;
__device__ int   g_is64;

// ---------------- f32x2 helpers ----------------
__device__ __forceinline__ unsigned long long pack2(float a, float b) {
    unsigned long long r;
    asm("mov.b64 %0, {%1, %2};" : "=l"(r) : "f"(a), "f"(b));
    return r;
}
__device__ __forceinline__ void unpack2(unsigned long long v, float& a, float& b) {
    asm("mov.b64 {%0, %1}, %2;" : "=f"(a), "=f"(b) : "l"(v));
}
__device__ __forceinline__ unsigned long long fma2(
    unsigned long long a, unsigned long long b, unsigned long long c) {
    unsigned long long d;
    asm("fma.rn.f32x2 %0, %1, %2, %3;" : "=l"(d) : "l"(a), "l"(b), "l"(c));
    return d;
}

// ---------------- fused pre-pass: zero counts, dtype probe, cedge ----------------
__global__ void k_pre(const int* __restrict__ ei32,
                      const float* __restrict__ w_edge,
                      const float* __restrict__ att_edge) {
    int i = blockIdx.x * blockDim.x + threadIdx.x;
    if (i < NN) g_counts[i] = 0;

    if (blockIdx.x == 0) {
        __shared__ int nz;
        if (threadIdx.x == 0) nz = 0;
        __syncthreads();
        int found = 0;
        for (int t = threadIdx.x; t < 4096; t += blockDim.x)
            if (ei32[2 * t + 1] != 0) found = 1;
        if (found) atomicAdd(&nz, 1);
        __syncthreads();
        if (threadIdx.x == 0) g_is64 = (nz == 0) ? 1 : 0;
    } else if (blockIdx.x == 1 && threadIdx.x < 128) {
        float v = w_edge[threadIdx.x] * att_edge[threadIdx.x];
#pragma unroll
        for (int o = 16; o > 0; o >>= 1) v += __shfl_xor_sync(FULLM, v, o);
        __shared__ float s4[4];
        if ((threadIdx.x & 31) == 0) s4[threadIdx.x >> 5] = v;
        __syncthreads();
        if (threadIdx.x == 0) g_cedge = s4[0] + s4[1] + s4[2] + s4[3];
    }
}

// degree histogram only
__global__ void k_convert(const void* __restrict__ ei) {
    int e = blockIdx.x * blockDim.x + threadIdx.x;
    if (e >= EE) return;
    int d;
    if (g_is64) d = (int)((const long long*)ei)[EE + e];
    else        d = ((const int*)ei)[EE + e];
    atomicAdd(&g_counts[d], 1);
}

// warp per node: h = x @ w_gat, a_src/a_dst dots
__global__ __launch_bounds__(256) void k_node_transform(
    const float* __restrict__ x, const float* __restrict__ w_gat,
    const float* __restrict__ att_src, const float* __restrict__ att_dst) {
    int n = blockIdx.x * 8 + (threadIdx.x >> 5);
    if (n >= NN) return;
    int lane = threadIdx.x & 31;
    float xr[DIN];
#pragma unroll
    for (int k = 0; k < DIN; k++) xr[k] = x[n * DIN + k];
    float asum = 0.f, dsum = 0.f;
#pragma unroll
    for (int c = 0; c < 4; c++) {
        int j = lane + 32 * c;
        float hj = 0.f;
#pragma unroll
        for (int k = 0; k < DIN; k++) hj += xr[k] * w_gat[k * HID + j];
        g_h[(size_t)n * HID + j] = hj;
        asum += hj * att_src[j];
        dsum += hj * att_dst[j];
    }
#pragma unroll
    for (int o = 16; o > 0; o >>= 1) {
        asum += __shfl_xor_sync(FULLM, asum, o);
        dsum += __shfl_xor_sync(FULLM, dsum, o);
    }
    if (lane == 0) { g_asrc[n] = asum; g_adst[n] = dsum; }
}

__global__ void k_scan1() {
    __shared__ int s[SCAN_B];
    int tid = threadIdx.x;
    int gi = blockIdx.x * SCAN_B + tid;
    int v = (gi < NN) ? g_counts[gi] : 0;
    s[tid] = v;
    __syncthreads();
    for (int off = 1; off < SCAN_B; off <<= 1) {
        int t = (tid >= off) ? s[tid - off] : 0;
        __syncthreads();
        s[tid] += t;
        __syncthreads();
    }
    if (gi < NN) g_offsets[gi] = s[tid] - v;
    if (tid == SCAN_B - 1) g_bsum[blockIdx.x] = s[tid];
}

__global__ void k_scan3() {
    __shared__ int spre;
    int tid = threadIdx.x;
    if (tid == 0) spre = 0;
    __syncthreads();
    if (tid < NB && tid < blockIdx.x) atomicAdd(&spre, g_bsum[tid]);
    __syncthreads();
    int pre = spre;
    int gi = blockIdx.x * SCAN_B + tid;
    if (gi < NN) {
        int o = g_offsets[gi] + pre;
        g_offsets[gi] = o;
        g_cursor[gi]  = o;
        g_ind[gi]     = (g_counts[gi] > 0) ? 1.f : 0.f;
    }
    if (gi == 0) g_offsets[NN] = EE;
}

// scatter + fused logit/exp; single ST.128 per edge
__global__ void k_scatter(const void* __restrict__ ei, const float* __restrict__ ew) {
    int e = blockIdx.x * blockDim.x + threadIdx.x;
    if (e >= EE) return;
    int s, d;
    if (g_is64) {
        const long long* p = (const long long*)ei;
        s = (int)p[e];
        d = (int)p[EE + e];
    } else {
        const int* p = (const int*)ei;
        s = p[e];
        d = p[EE + e];
    }
    float l = g_asrc[s] + g_adst[d] + g_cedge * ew[e];
    l = (l > 0.f) ? l : SLOPE * l;
    float ev = __expf(l);
    int pos = atomicAdd(&g_cursor[d], 1);
    int4 rec;
    rec.x = s;
    rec.y = __float_as_int(ev);
    rec.z = e;
    rec.w = 0;
    g_edge[pos] = rec;
}

// warp per dst node: GAT aggregation. Uniform (broadcast) edge loads, no shuffles.
// Aggregate with raw exp values, scale by invd at the end; normalized alpha
// written back in a separate coalesced pass.
__global__ __launch_bounds__(256) void k_gat(const float* __restrict__ b_gat) {
    int n = blockIdx.x * 8 + (threadIdx.x >> 5);
    if (n >= NN) return;
    int lane = threadIdx.x & 31;
    int off = g_offsets[n];
    int deg = g_offsets[n + 1] - off;

    // denom (lane-strided, coalesced)
    float lsum = 0.f;
    for (int i = lane; i < deg; i += 32)
        lsum += __int_as_float(g_edge[off + i].y);
#pragma unroll
    for (int o = 16; o > 0; o >>= 1) lsum += __shfl_xor_sync(FULLM, lsum, o);
    float invd = 1.f / fmaxf(lsum, 1e-16f);

    unsigned long long acc0 = pack2(0.f, 0.f), acc1 = acc0;
    int i = 0;
    for (; i + 4 <= deg; i += 4) {
        int4 e0 = g_edge[off + i];
        int4 e1 = g_edge[off + i + 1];
        int4 e2 = g_edge[off + i + 2];
        int4 e3 = g_edge[off + i + 3];
        ulonglong2 h0 = *(const ulonglong2*)&g_h[(size_t)e0.x * HID + lane * 4];
        ulonglong2 h1 = *(const ulonglong2*)&g_h[(size_t)e1.x * HID + lane * 4];
        ulonglong2 h2 = *(const ulonglong2*)&g_h[(size_t)e2.x * HID + lane * 4];
        ulonglong2 h3 = *(const ulonglong2*)&g_h[(size_t)e3.x * HID + lane * 4];
        float a0 = __int_as_float(e0.y), a1 = __int_as_float(e1.y);
        float a2 = __int_as_float(e2.y), a3 = __int_as_float(e3.y);
        unsigned long long p0 = pack2(a0, a0), p1 = pack2(a1, a1);
        unsigned long long p2 = pack2(a2, a2), p3 = pack2(a3, a3);
        acc0 = fma2(p0, h0.x, acc0); acc1 = fma2(p0, h0.y, acc1);
        acc0 = fma2(p1, h1.x, acc0); acc1 = fma2(p1, h1.y, acc1);
        acc0 = fma2(p2, h2.x, acc0); acc1 = fma2(p2, h2.y, acc1);
        acc0 = fma2(p3, h3.x, acc0); acc1 = fma2(p3, h3.y, acc1);
    }
    for (; i < deg; i++) {
        int4 e0 = g_edge[off + i];
        ulonglong2 h0 = *(const ulonglong2*)&g_h[(size_t)e0.x * HID + lane * 4];
        float a0 = __int_as_float(e0.y);
        unsigned long long p0 = pack2(a0, a0);
        acc0 = fma2(p0, h0.x, acc0); acc1 = fma2(p0, h0.y, acc1);
    }

    float4 b4 = *(const float4*)&b_gat[lane * 4];
    float4 r;
    unpack2(acc0, r.x, r.y);
    unpack2(acc1, r.z, r.w);
    r.x = fmaxf(r.x * invd + b4.x, 0.f);
    r.y = fmaxf(r.y * invd + b4.y, 0.f);
    r.z = fmaxf(r.z * invd + b4.z, 0.f);
    r.w = fmaxf(r.w * invd + b4.w, 0.f);
    *(float4*)&g_h1[(size_t)n * HID + lane * 4] = r;

    // normalized alpha writeback (needed for outputs and GCN pass)
    for (int j = lane; j < deg; j += 32) {
        float a = __int_as_float(g_edge[off + j].y) * invd;
        g_edge[off + j].y = __float_as_int(a);
    }
}

// hx = ind[row] * (h1 @ w_gcn): 32 nodes/block, smem pre-duplicated f32x2 pairs
__global__ __launch_bounds__(256) void k_gemm(const float* __restrict__ w_gcn) {
    int n0 = blockIdx.x * 32;
    __shared__ unsigned long long shd[HID][34];
    for (int i = threadIdx.x; i < 32 * HID; i += 256) {
        int nn = i >> 7, kk = i & 127;
        float v = g_h1[(size_t)n0 * HID + i];
        shd[kk][nn] = pack2(v, v);
    }
    __syncthreads();

    int cg = threadIdx.x & 31;
    int ng = threadIdx.x >> 5;
    int jc = cg * 4;
    unsigned long long z = pack2(0.f, 0.f);
    unsigned long long acc[4][2];
#pragma unroll
    for (int r = 0; r < 4; r++) { acc[r][0] = z; acc[r][1] = z; }

#pragma unroll 4
    for (int k = 0; k < HID; k++) {
        ulonglong2 wv  = *(const ulonglong2*)&w_gcn[k * HID + jc];
        ulonglong2 p01 = *(const ulonglong2*)&shd[k][ng * 4];
        ulonglong2 p23 = *(const ulonglong2*)&shd[k][ng * 4 + 2];
        acc[0][0] = fma2(p01.x, wv.x, acc[0][0]);
        acc[0][1] = fma2(p01.x, wv.y, acc[0][1]);
        acc[1][0] = fma2(p01.y, wv.x, acc[1][0]);
        acc[1][1] = fma2(p01.y, wv.y, acc[1][1]);
        acc[2][0] = fma2(p23.x, wv.x, acc[2][0]);
        acc[2][1] = fma2(p23.x, wv.y, acc[2][1]);
        acc[3][0] = fma2(p23.y, wv.x, acc[3][0]);
        acc[3][1] = fma2(p23.y, wv.y, acc[3][1]);
    }
#pragma unroll
    for (int r = 0; r < 4; r++) {
        int row = n0 + ng * 4 + r;
        float ind = g_ind[row];
        float4 o;
        unpack2(acc[r][0], o.x, o.y);
        unpack2(acc[r][1], o.z, o.w);
        o.x *= ind; o.y *= ind; o.z *= ind; o.w *= ind;
        *(float4*)&g_hx[(size_t)row * HID + jc] = o;
    }
}

// warp per dst node: GCN aggregation + relu + output head (uniform edge loads)
__global__ __launch_bounds__(256) void k_gcn_out(
    const float* __restrict__ b_gcn, const float* __restrict__ w_out,
    const float* __restrict__ b_out, float* __restrict__ out) {
    int n = blockIdx.x * 8 + (threadIdx.x >> 5);
    if (n >= NN) return;
    int lane = threadIdx.x & 31;
    int off = g_offsets[n];
    int deg = g_offsets[n + 1] - off;

    unsigned long long acc0 = pack2(0.f, 0.f), acc1 = acc0;
    int i = 0;
    for (; i + 4 <= deg; i += 4) {
        int4 e0 = g_edge[off + i];
        int4 e1 = g_edge[off + i + 1];
        int4 e2 = g_edge[off + i + 2];
        int4 e3 = g_edge[off + i + 3];
        ulonglong2 h0 = *(const ulonglong2*)&g_hx[(size_t)e0.x * HID + lane * 4];
        ulonglong2 h1 = *(const ulonglong2*)&g_hx[(size_t)e1.x * HID + lane * 4];
        ulonglong2 h2 = *(const ulonglong2*)&g_hx[(size_t)e2.x * HID + lane * 4];
        ulonglong2 h3 = *(const ulonglong2*)&g_hx[(size_t)e3.x * HID + lane * 4];
        float a0 = __int_as_float(e0.y), a1 = __int_as_float(e1.y);
        float a2 = __int_as_float(e2.y), a3 = __int_as_float(e3.y);
        unsigned long long p0 = pack2(a0, a0), p1 = pack2(a1, a1);
        unsigned long long p2 = pack2(a2, a2), p3 = pack2(a3, a3);
        acc0 = fma2(p0, h0.x, acc0); acc1 = fma2(p0, h0.y, acc1);
        acc0 = fma2(p1, h1.x, acc0); acc1 = fma2(p1, h1.y, acc1);
        acc0 = fma2(p2, h2.x, acc0); acc1 = fma2(p2, h2.y, acc1);
        acc0 = fma2(p3, h3.x, acc0); acc1 = fma2(p3, h3.y, acc1);
    }
    for (; i < deg; i++) {
        int4 e0 = g_edge[off + i];
        ulonglong2 h0 = *(const ulonglong2*)&g_hx[(size_t)e0.x * HID + lane * 4];
        float a0 = __int_as_float(e0.y);
        unsigned long long p0 = pack2(a0, a0);
        acc0 = fma2(p0, h0.x, acc0); acc1 = fma2(p0, h0.y, acc1);
    }

    float4 b4 = *(const float4*)&b_gcn[lane * 4];
    float4 h2;
    unpack2(acc0, h2.x, h2.y);
    unpack2(acc1, h2.z, h2.w);
    h2.x = fmaxf(h2.x + b4.x, 0.f);
    h2.y = fmaxf(h2.y + b4.y, 0.f);
    h2.z = fmaxf(h2.z + b4.z, 0.f);
    h2.w = fmaxf(h2.w + b4.w, 0.f);

    int jc = lane * 4;
    float v0 = h2.x * w_out[(jc + 0) * 2] + h2.y * w_out[(jc + 1) * 2]
             + h2.z * w_out[(jc + 2) * 2] + h2.w * w_out[(jc + 3) * 2];
    float v1 = h2.x * w_out[(jc + 0) * 2 + 1] + h2.y * w_out[(jc + 1) * 2 + 1]
             + h2.z * w_out[(jc + 2) * 2 + 1] + h2.w * w_out[(jc + 3) * 2 + 1];
#pragma unroll
    for (int o = 16; o > 0; o >>= 1) {
        v0 += __shfl_xor_sync(FULLM, v0, o);
        v1 += __shfl_xor_sync(FULLM, v1, o);
    }
    if (lane == 0) {
        out[n * 2 + 0] = v0 + b_out[0];
        out[n * 2 + 1] = v1 + b_out[1];
    }
}

__global__ void k_copy_ei_f(const void* __restrict__ ei, float* __restrict__ dst) {
    int i = blockIdx.x * blockDim.x + threadIdx.x;
    if (i >= 2 * EE) return;
    if (g_is64) dst[i] = (float)((const long long*)ei)[i];
    else        dst[i] = (float)((const int*)ei)[i];
}

__global__ void k_copy_alpha(float* __restrict__ dst) {
    int i = blockIdx.x * blockDim.x + threadIdx.x;
    if (i < EE) {
        int4 e = g_edge[i];
        dst[e.z] = __int_as_float(e.y);
    }
}

// ---------------- launch ----------------
extern "C" void kernel_launch(void* const* d_in, const int* in_sizes, int n_in,
                              void* d_out, int out_size) {
    int iei, iew, iwg, ias, iad, iwe, iae, ibg, iwgcn, ibgcn, iwo, ibo;
    if (in_sizes[1] == 2 * EE) {
        iei = 1; iew = 2; iwg = 3; ias = 4; iad = 5; iwe = 6; iae = 7;
        ibg = 8; iwgcn = 9; ibgcn = 10; iwo = 11; ibo = 12;
    } else {
        iew = 1; iwg = 2; ias = 3; iad = 4; iwe = 5; iae = 6; ibg = 7;
        iwgcn = 8; ibgcn = 9; iwo = 10; ibo = 11; iei = 12;
    }

    const float* x        = (const float*)d_in[0];
    const void*  ei       = d_in[iei];
    const float* ew       = (const float*)d_in[iew];
    const float* w_gat    = (const float*)d_in[iwg];
    const float* att_src  = (const float*)d_in[ias];
    const float* att_dst  = (const float*)d_in[iad];
    const float* w_edge   = (const float*)d_in[iwe];
    const float* att_edge = (const float*)d_in[iae];
    const float* b_gat    = (const float*)d_in[ibg];
    const float* w_gcn    = (const float*)d_in[iwgcn];
    const float* b_gcn    = (const float*)d_in[ibgcn];
    const float* w_out    = (const float*)d_in[iwo];
    const float* b_out    = (const float*)d_in[ibo];
    float*       out      = (float*)d_out;

    k_pre<<<(NN + 255) / 256, 256>>>((const int*)ei, w_edge, att_edge);
    k_convert<<<(EE + 255) / 256, 256>>>(ei);
    k_node_transform<<<NN / 8, 256>>>(x, w_gat, att_src, att_dst);
    k_scan1<<<NB, SCAN_B>>>();
    k_scan3<<<NB, SCAN_B>>>();
    k_scatter<<<(EE + 255) / 256, 256>>>(ei, ew);
    k_gat<<<NN / 8, 256>>>(b_gat);
    k_gemm<<<NN / 32, 256>>>(w_gcn);
    k_gcn_out<<<NN / 8, 256>>>(b_gcn, w_out, b_out, out);

    int rem = out_size - NN * OUTD;
    if (rem == EE) {
        k_copy_alpha<<<(EE + 255) / 256, 256>>>(out + NN * OUTD);
    } else if (rem == 3 * EE) {
        k_copy_ei_f<<<(2 * EE + 255) / 256, 256>>>(ei, out + NN * OUTD);
        k_copy_alpha<<<(EE + 255) / 256, 256>>>(out + NN * OUTD + 2 * EE);
    }
}

// round 8
// speedup vs baseline: 2.0006x; 1.0006x over previous
#include <cuda_runtime.h>
#include <math.h>

#define NN   100000
#define EE   1600000
#define HID  128
#define DIN  6
#define OUTD 2
#define SLOPE 0.2f

#define SCAN_B 1024
#define NB ((NN + SCAN_B - 1) / SCAN_B)   // 98
#define FULLM 0xffffffffu

// ---------------- device scratch ----------------
__device__ float g_h    [NN * HID];
__device__ float g_h1   [NN * HID];
__device__ float g_hx   [NN * HID];
__device__ float g_asrc [NN];
__device__ float g_adst [NN];
__device__ float g_ind  [NN];
__device__ int4  g_edge [EE];         // {src, exp_bits, eid, 0} in CSR order
__device__ float g_alphan[EE];        // normalized alpha, CSR order (coalesced)
__device__ int   g_counts [NN];
__device__ int   g_offsets[NN + 1];
__device__ int   g_cursor [NN];
__device__ int   g_bsum   [NB];
__device__ float g_cedge;
__device__ int   g_is64;

// ---------------- f32x2 helpers ----------------
__device__ __forceinline__ unsigned long long pack2(float a, float b) {
    unsigned long long r;
    asm("mov.b64 %0, {%1, %2};" : "=l"(r) : "f"(a), "f"(b));
    return r;
}
__device__ __forceinline__ void unpack2(unsigned long long v, float& a, float& b) {
    asm("mov.b64 {%0, %1}, %2;" : "=f"(a), "=f"(b) : "l"(v));
}
__device__ __forceinline__ unsigned long long fma2(
    unsigned long long a, unsigned long long b, unsigned long long c) {
    unsigned long long d;
    asm("fma.rn.f32x2 %0, %1, %2, %3;" : "=l"(d) : "l"(a), "l"(b), "l"(c));
    return d;
}

// ---------------- fused pre-pass: zero counts, dtype probe, cedge ----------------
__global__ void k_pre(const int* __restrict__ ei32,
                      const float* __restrict__ w_edge,
                      const float* __restrict__ att_edge) {
    int i = blockIdx.x * blockDim.x + threadIdx.x;
    if (i < NN) g_counts[i] = 0;

    if (blockIdx.x == 0) {
        __shared__ int nz;
        if (threadIdx.x == 0) nz = 0;
        __syncthreads();
        int found = 0;
        for (int t = threadIdx.x; t < 4096; t += blockDim.x)
            if (ei32[2 * t + 1] != 0) found = 1;
        if (found) atomicAdd(&nz, 1);
        __syncthreads();
        if (threadIdx.x == 0) g_is64 = (nz == 0) ? 1 : 0;
    } else if (blockIdx.x == 1 && threadIdx.x < 128) {
        float v = w_edge[threadIdx.x] * att_edge[threadIdx.x];
#pragma unroll
        for (int o = 16; o > 0; o >>= 1) v += __shfl_xor_sync(FULLM, v, o);
        __shared__ float s4[4];
        if ((threadIdx.x & 31) == 0) s4[threadIdx.x >> 5] = v;
        __syncthreads();
        if (threadIdx.x == 0) g_cedge = s4[0] + s4[1] + s4[2] + s4[3];
    }
}

// degree histogram
__global__ void k_convert(const void* __restrict__ ei) {
    int e = blockIdx.x * blockDim.x + threadIdx.x;
    if (e >= EE) return;
    int d;
    if (g_is64) d = (int)((const long long*)ei)[EE + e];
    else        d = ((const int*)ei)[EE + e];
    atomicAdd(&g_counts[d], 1);
}

// warp per node: h = x @ w_gat, a_src/a_dst dots
__global__ __launch_bounds__(256) void k_node_transform(
    const float* __restrict__ x, const float* __restrict__ w_gat,
    const float* __restrict__ att_src, const float* __restrict__ att_dst) {
    int n = blockIdx.x * 8 + (threadIdx.x >> 5);
    if (n >= NN) return;
    int lane = threadIdx.x & 31;
    float xr[DIN];
#pragma unroll
    for (int k = 0; k < DIN; k++) xr[k] = x[n * DIN + k];
    float asum = 0.f, dsum = 0.f;
#pragma unroll
    for (int c = 0; c < 4; c++) {
        int j = lane + 32 * c;
        float hj = 0.f;
#pragma unroll
        for (int k = 0; k < DIN; k++) hj += xr[k] * w_gat[k * HID + j];
        g_h[(size_t)n * HID + j] = hj;
        asum += hj * att_src[j];
        dsum += hj * att_dst[j];
    }
#pragma unroll
    for (int o = 16; o > 0; o >>= 1) {
        asum += __shfl_xor_sync(FULLM, asum, o);
        dsum += __shfl_xor_sync(FULLM, dsum, o);
    }
    if (lane == 0) { g_asrc[n] = asum; g_adst[n] = dsum; }
}

__global__ void k_scan1() {
    __shared__ int s[SCAN_B];
    int tid = threadIdx.x;
    int gi = blockIdx.x * SCAN_B + tid;
    int v = (gi < NN) ? g_counts[gi] : 0;
    s[tid] = v;
    __syncthreads();
    for (int off = 1; off < SCAN_B; off <<= 1) {
        int t = (tid >= off) ? s[tid - off] : 0;
        __syncthreads();
        s[tid] += t;
        __syncthreads();
    }
    if (gi < NN) g_offsets[gi] = s[tid] - v;
    if (tid == SCAN_B - 1) g_bsum[blockIdx.x] = s[tid];
}

__global__ void k_scan3() {
    __shared__ int spre;
    int tid = threadIdx.x;
    if (tid == 0) spre = 0;
    __syncthreads();
    if (tid < NB && tid < blockIdx.x) atomicAdd(&spre, g_bsum[tid]);
    __syncthreads();
    int pre = spre;
    int gi = blockIdx.x * SCAN_B + tid;
    if (gi < NN) {
        int o = g_offsets[gi] + pre;
        g_offsets[gi] = o;
        g_cursor[gi]  = o;
        g_ind[gi]     = (g_counts[gi] > 0) ? 1.f : 0.f;
    }
    if (gi == 0) g_offsets[NN] = EE;
}

// scatter + fused logit/exp; single ST.128 per edge
__global__ void k_scatter(const void* __restrict__ ei, const float* __restrict__ ew) {
    int e = blockIdx.x * blockDim.x + threadIdx.x;
    if (e >= EE) return;
    int s, d;
    if (g_is64) {
        const long long* p = (const long long*)ei;
        s = (int)p[e];
        d = (int)p[EE + e];
    } else {
        const int* p = (const int*)ei;
        s = p[e];
        d = p[EE + e];
    }
    float l = g_asrc[s] + g_adst[d] + g_cedge * ew[e];
    l = (l > 0.f) ? l : SLOPE * l;
    float ev = __expf(l);
    int pos = atomicAdd(&g_cursor[d], 1);
    int4 rec;
    rec.x = s;
    rec.y = __float_as_int(ev);
    rec.z = e;
    rec.w = 0;
    g_edge[pos] = rec;
}

// warp per dst node: GAT aggregation; normalized alpha -> separate coalesced array
__global__ __launch_bounds__(256) void k_gat(const float* __restrict__ b_gat) {
    int n = blockIdx.x * 8 + (threadIdx.x >> 5);
    if (n >= NN) return;
    int lane = threadIdx.x & 31;
    int off = g_offsets[n];
    int deg = g_offsets[n + 1] - off;

    float lsum = 0.f;
    for (int i = lane; i < deg; i += 32)
        lsum += __int_as_float(g_edge[off + i].y);
#pragma unroll
    for (int o = 16; o > 0; o >>= 1) lsum += __shfl_xor_sync(FULLM, lsum, o);
    float invd = 1.f / fmaxf(lsum, 1e-16f);

    unsigned long long acc0 = pack2(0.f, 0.f), acc1 = acc0;
    int i = 0;
    for (; i + 4 <= deg; i += 4) {
        int4 e0 = g_edge[off + i];
        int4 e1 = g_edge[off + i + 1];
        int4 e2 = g_edge[off + i + 2];
        int4 e3 = g_edge[off + i + 3];
        ulonglong2 h0 = *(const ulonglong2*)&g_h[(size_t)e0.x * HID + lane * 4];
        ulonglong2 h1 = *(const ulonglong2*)&g_h[(size_t)e1.x * HID + lane * 4];
        ulonglong2 h2 = *(const ulonglong2*)&g_h[(size_t)e2.x * HID + lane * 4];
        ulonglong2 h3 = *(const ulonglong2*)&g_h[(size_t)e3.x * HID + lane * 4];
        float a0 = __int_as_float(e0.y), a1 = __int_as_float(e1.y);
        float a2 = __int_as_float(e2.y), a3 = __int_as_float(e3.y);
        unsigned long long p0 = pack2(a0, a0), p1 = pack2(a1, a1);
        unsigned long long p2 = pack2(a2, a2), p3 = pack2(a3, a3);
        acc0 = fma2(p0, h0.x, acc0); acc1 = fma2(p0, h0.y, acc1);
        acc0 = fma2(p1, h1.x, acc0); acc1 = fma2(p1, h1.y, acc1);
        acc0 = fma2(p2, h2.x, acc0); acc1 = fma2(p2, h2.y, acc1);
        acc0 = fma2(p3, h3.x, acc0); acc1 = fma2(p3, h3.y, acc1);
    }
    for (; i < deg; i++) {
        int4 e0 = g_edge[off + i];
        ulonglong2 h0 = *(const ulonglong2*)&g_h[(size_t)e0.x * HID + lane * 4];
        float a0 = __int_as_float(e0.y);
        unsigned long long p0 = pack2(a0, a0);
        acc0 = fma2(p0, h0.x, acc0); acc1 = fma2(p0, h0.y, acc1);
    }

    float4 b4 = *(const float4*)&b_gat[lane * 4];
    float4 r;
    unpack2(acc0, r.x, r.y);
    unpack2(acc1, r.z, r.w);
    r.x = fmaxf(r.x * invd + b4.x, 0.f);
    r.y = fmaxf(r.y * invd + b4.y, 0.f);
    r.z = fmaxf(r.z * invd + b4.z, 0.f);
    r.w = fmaxf(r.w * invd + b4.w, 0.f);
    *(float4*)&g_h1[(size_t)n * HID + lane * 4] = r;

    // coalesced normalized-alpha store (no RMW into the AoS records)
    for (int j = lane; j < deg; j += 32)
        g_alphan[off + j] = __int_as_float(g_edge[off + j].y) * invd;
}

// hx = ind[row] * (h1 @ w_gcn): 32 nodes/block, smem pre-duplicated f32x2 pairs
__global__ __launch_bounds__(256) void k_gemm(const float* __restrict__ w_gcn) {
    int n0 = blockIdx.x * 32;
    __shared__ unsigned long long shd[HID][34];
    for (int i = threadIdx.x; i < 32 * HID; i += 256) {
        int nn = i >> 7, kk = i & 127;
        float v = g_h1[(size_t)n0 * HID + i];
        shd[kk][nn] = pack2(v, v);
    }
    __syncthreads();

    int cg = threadIdx.x & 31;
    int ng = threadIdx.x >> 5;
    int jc = cg * 4;
    unsigned long long z = pack2(0.f, 0.f);
    unsigned long long acc[4][2];
#pragma unroll
    for (int r = 0; r < 4; r++) { acc[r][0] = z; acc[r][1] = z; }

#pragma unroll 4
    for (int k = 0; k < HID; k++) {
        ulonglong2 wv  = *(const ulonglong2*)&w_gcn[k * HID + jc];
        ulonglong2 p01 = *(const ulonglong2*)&shd[k][ng * 4];
        ulonglong2 p23 = *(const ulonglong2*)&shd[k][ng * 4 + 2];
        acc[0][0] = fma2(p01.x, wv.x, acc[0][0]);
        acc[0][1] = fma2(p01.x, wv.y, acc[0][1]);
        acc[1][0] = fma2(p01.y, wv.x, acc[1][0]);
        acc[1][1] = fma2(p01.y, wv.y, acc[1][1]);
        acc[2][0] = fma2(p23.x, wv.x, acc[2][0]);
        acc[2][1] = fma2(p23.x, wv.y, acc[2][1]);
        acc[3][0] = fma2(p23.y, wv.x, acc[3][0]);
        acc[3][1] = fma2(p23.y, wv.y, acc[3][1]);
    }
#pragma unroll
    for (int r = 0; r < 4; r++) {
        int row = n0 + ng * 4 + r;
        float ind = g_ind[row];
        float4 o;
        unpack2(acc[r][0], o.x, o.y);
        unpack2(acc[r][1], o.z, o.w);
        o.x *= ind; o.y *= ind; o.z *= ind; o.w *= ind;
        *(float4*)&g_hx[(size_t)row * HID + jc] = o;
    }
}

// warp per dst node: GCN aggregation + relu + output head
__global__ __launch_bounds__(256) void k_gcn_out(
    const float* __restrict__ b_gcn, const float* __restrict__ w_out,
    const float* __restrict__ b_out, float* __restrict__ out) {
    int n = blockIdx.x * 8 + (threadIdx.x >> 5);
    if (n >= NN) return;
    int lane = threadIdx.x & 31;
    int off = g_offsets[n];
    int deg = g_offsets[n + 1] - off;

    unsigned long long acc0 = pack2(0.f, 0.f), acc1 = acc0;
    int i = 0;
    for (; i + 4 <= deg; i += 4) {
        int s0 = g_edge[off + i].x;
        int s1 = g_edge[off + i + 1].x;
        int s2 = g_edge[off + i + 2].x;
        int s3 = g_edge[off + i + 3].x;
        float a0 = g_alphan[off + i];
        float a1 = g_alphan[off + i + 1];
        float a2 = g_alphan[off + i + 2];
        float a3 = g_alphan[off + i + 3];
        ulonglong2 h0 = *(const ulonglong2*)&g_hx[(size_t)s0 * HID + lane * 4];
        ulonglong2 h1 = *(const ulonglong2*)&g_hx[(size_t)s1 * HID + lane * 4];
        ulonglong2 h2 = *(const ulonglong2*)&g_hx[(size_t)s2 * HID + lane * 4];
        ulonglong2 h3 = *(const ulonglong2*)&g_hx[(size_t)s3 * HID + lane * 4];
        unsigned long long p0 = pack2(a0, a0), p1 = pack2(a1, a1);
        unsigned long long p2 = pack2(a2, a2), p3 = pack2(a3, a3);
        acc0 = fma2(p0, h0.x, acc0); acc1 = fma2(p0, h0.y, acc1);
        acc0 = fma2(p1, h1.x, acc0); acc1 = fma2(p1, h1.y, acc1);
        acc0 = fma2(p2, h2.x, acc0); acc1 = fma2(p2, h2.y, acc1);
        acc0 = fma2(p3, h3.x, acc0); acc1 = fma2(p3, h3.y, acc1);
    }
    for (; i < deg; i++) {
        int s0 = g_edge[off + i].x;
        float a0 = g_alphan[off + i];
        ulonglong2 h0 = *(const ulonglong2*)&g_hx[(size_t)s0 * HID + lane * 4];
        unsigned long long p0 = pack2(a0, a0);
        acc0 = fma2(p0, h0.x, acc0); acc1 = fma2(p0, h0.y, acc1);
    }

    float4 b4 = *(const float4*)&b_gcn[lane * 4];
    float4 h2;
    unpack2(acc0, h2.x, h2.y);
    unpack2(acc1, h2.z, h2.w);
    h2.x = fmaxf(h2.x + b4.x, 0.f);
    h2.y = fmaxf(h2.y + b4.y, 0.f);
    h2.z = fmaxf(h2.z + b4.z, 0.f);
    h2.w = fmaxf(h2.w + b4.w, 0.f);

    int jc = lane * 4;
    float v0 = h2.x * w_out[(jc + 0) * 2] + h2.y * w_out[(jc + 1) * 2]
             + h2.z * w_out[(jc + 2) * 2] + h2.w * w_out[(jc + 3) * 2];
    float v1 = h2.x * w_out[(jc + 0) * 2 + 1] + h2.y * w_out[(jc + 1) * 2 + 1]
             + h2.z * w_out[(jc + 2) * 2 + 1] + h2.w * w_out[(jc + 3) * 2 + 1];
#pragma unroll
    for (int o = 16; o > 0; o >>= 1) {
        v0 += __shfl_xor_sync(FULLM, v0, o);
        v1 += __shfl_xor_sync(FULLM, v1, o);
    }
    if (lane == 0) {
        out[n * 2 + 0] = v0 + b_out[0];
        out[n * 2 + 1] = v1 + b_out[1];
    }
}

__global__ void k_copy_ei_f(const void* __restrict__ ei, float* __restrict__ dst) {
    int i = blockIdx.x * blockDim.x + threadIdx.x;
    if (i >= 2 * EE) return;
    if (g_is64) dst[i] = (float)((const long long*)ei)[i];
    else        dst[i] = (float)((const int*)ei)[i];
}

__global__ void k_copy_alpha(float* __restrict__ dst) {
    int i = blockIdx.x * blockDim.x + threadIdx.x;
    if (i < EE) dst[g_edge[i].z] = g_alphan[i];
}

// ---------------- launch ----------------
extern "C" void kernel_launch(void* const* d_in, const int* in_sizes, int n_in,
                              void* d_out, int out_size) {
    // one-time host-side resources (no device memory)
    static cudaStream_t s1 = 0, s2 = 0, s3 = 0;
    static cudaEvent_t evPre = 0, evNT = 0, evEi = 0, evGat = 0, evAl = 0;
    if (s1 == 0) {
        cudaStreamCreateWithFlags(&s1, cudaStreamNonBlocking);
        cudaStreamCreateWithFlags(&s2, cudaStreamNonBlocking);
        cudaStreamCreateWithFlags(&s3, cudaStreamNonBlocking);
        cudaEventCreateWithFlags(&evPre, cudaEventDisableTiming);
        cudaEventCreateWithFlags(&evNT,  cudaEventDisableTiming);
        cudaEventCreateWithFlags(&evEi,  cudaEventDisableTiming);
        cudaEventCreateWithFlags(&evGat, cudaEventDisableTiming);
        cudaEventCreateWithFlags(&evAl,  cudaEventDisableTiming);
    }

    int iei, iew, iwg, ias, iad, iwe, iae, ibg, iwgcn, ibgcn, iwo, ibo;
    if (in_sizes[1] == 2 * EE) {
        iei = 1; iew = 2; iwg = 3; ias = 4; iad = 5; iwe = 6; iae = 7;
        ibg = 8; iwgcn = 9; ibgcn = 10; iwo = 11; ibo = 12;
    } else {
        iew = 1; iwg = 2; ias = 3; iad = 4; iwe = 5; iae = 6; ibg = 7;
        iwgcn = 8; ibgcn = 9; iwo = 10; ibo = 11; iei = 12;
    }

    const float* x        = (const float*)d_in[0];
    const void*  ei       = d_in[iei];
    const float* ew       = (const float*)d_in[iew];
    const float* w_gat    = (const float*)d_in[iwg];
    const float* att_src  = (const float*)d_in[ias];
    const float* att_dst  = (const float*)d_in[iad];
    const float* w_edge   = (const float*)d_in[iwe];
    const float* att_edge = (const float*)d_in[iae];
    const float* b_gat    = (const float*)d_in[ibg];
    const float* w_gcn    = (const float*)d_in[iwgcn];
    const float* b_gcn    = (const float*)d_in[ibgcn];
    const float* w_out    = (const float*)d_in[iwo];
    const float* b_out    = (const float*)d_in[ibo];
    float*       out      = (float*)d_out;

    int rem = out_size - NN * OUTD;

    // main stream: pre -> convert -> scans -> scatter -> gat -> gemm -> gcn_out
    k_pre<<<(NN + 255) / 256, 256>>>((const int*)ei, w_edge, att_edge);
    cudaEventRecord(evPre, 0);

    // fork 1: node transform (independent of histogram/scan chain)
    cudaStreamWaitEvent(s1, evPre, 0);
    k_node_transform<<<NN / 8, 256, 0, s1>>>(x, w_gat, att_src, att_dst);
    cudaEventRecord(evNT, s1);

    // fork 2: edge_index float copy (independent)
    if (rem == 3 * EE) {
        cudaStreamWaitEvent(s2, evPre, 0);
        k_copy_ei_f<<<(2 * EE + 255) / 256, 256, 0, s2>>>(ei, out + NN * OUTD);
        cudaEventRecord(evEi, s2);
    }

    k_convert<<<(EE + 255) / 256, 256>>>(ei);
    k_scan1<<<NB, SCAN_B>>>();
    k_scan3<<<NB, SCAN_B>>>();

    cudaStreamWaitEvent(0, evNT, 0);       // scatter needs asrc/adst
    k_scatter<<<(EE + 255) / 256, 256>>>(ei, ew);
    k_gat<<<NN / 8, 256>>>(b_gat);
    cudaEventRecord(evGat, 0);

    // fork 3: alpha scatter-copy overlaps gemm + gcn
    if (rem == EE || rem == 3 * EE) {
        float* adst_out = (rem == EE) ? (out + NN * OUTD) : (out + NN * OUTD + 2 * EE);
        cudaStreamWaitEvent(s3, evGat, 0);
        k_copy_alpha<<<(EE + 255) / 256, 256, 0, s3>>>(adst_out);
        cudaEventRecord(evAl, s3);
    }

    k_gemm<<<NN / 32, 256>>>(w_gcn);
    k_gcn_out<<<NN / 8, 256>>>(b_gcn, w_out, b_out, out);

    // join forks back into the captured stream
    if (rem == EE || rem == 3 * EE) cudaStreamWaitEvent(0, evAl, 0);
    if (rem == 3 * EE)              cudaStreamWaitEvent(0, evEi, 0);
}